// round 9
// baseline (speedup 1.0000x reference)
#include <cuda_runtime.h>
#include <math.h>

#define BSZ 16
#define CW  32
#define MY  180
#define NX  360
#define KM  32
#define PLANE (MY*NX)
#define PIX (BSZ*PLANE)

__device__ __forceinline__ float geluf(float x) {
    return 0.5f * x * (1.0f + erff(x * 0.70710678118654752f));
}

__device__ __forceinline__ void cpa16(void* dst, const void* src, int szbytes) {
    unsigned d = (unsigned)__cvta_generic_to_shared(dst);
    asm volatile("cp.async.cg.shared.global [%0], [%1], 16, %2;"
                 :: "r"(d), "l"(src), "r"(szbytes) : "memory");
}
#define CPA_COMMIT() asm volatile("cp.async.commit_group;" ::: "memory")
#define CPA_WAIT0()  asm volatile("cp.async.wait_group 0;" ::: "memory")
#define CPA_WAIT1()  asm volatile("cp.async.wait_group 1;" ::: "memory")

// ---------------- device scratch ----------------
__device__ __align__(16) float g_h  [BSZ*CW*PLANE];
__device__ __align__(16) float g_x1 [BSZ*CW*PLANE];
__device__ __align__(16) float g_ftyr[BSZ*CW*KM*NX];
__device__ __align__(16) float g_ftyi[BSZ*CW*KM*NX];
__device__ __align__(16) float g_oyr [BSZ*CW*KM*NX];
__device__ __align__(16) float g_oyi [BSZ*CW*KM*NX];
__device__ __align__(16) float g_ftxr[BSZ*CW*KM*MY];
__device__ __align__(16) float g_ftxi[BSZ*CW*KM*MY];
__device__ __align__(16) float g_oxr [BSZ*CW*KM*MY];
__device__ __align__(16) float g_oxi [BSZ*CW*KM*MY];
__device__ __align__(16) float g_Vyr [KM*MY], g_Vyi [KM*MY];   // [k][m]
__device__ __align__(16) float g_Vymr[MY*KM], g_Vymi[MY*KM];   // [m][k]
__device__ __align__(16) float g_Vxr [KM*NX], g_Vxi [KM*NX];   // [k][n]
__device__ __align__(16) float g_Vxnr[NX*KM], g_Vxni[NX*KM];   // [n][k]
__device__ float g_gx[NX], g_gy[MY];

// ---------------- precompute ----------------
__global__ void precomputeK(const float* __restrict__ sx,
                            const float* __restrict__ sy) {
    int t = blockIdx.x * blockDim.x + threadIdx.x;
    int stride = gridDim.x * blockDim.x;
    float x0 = sx[0], xL = sx[NX - 1];
    float y0 = sy[0], yL = sy[MY - 1];
    float invRX = 1.0f / (xL - x0), invRY = 1.0f / (yL - y0);
    float invSqN = rsqrtf((float)NX), invSqM = rsqrtf((float)MY);
    const float TWO_PI = 6.283185307179586f;

    for (int idx = t; idx < KM * NX; idx += stride) {
        int k = idx / NX, n = idx % NX;
        float p = (sx[n] - x0) * invRX;
        float s, c; sincosf(-TWO_PI * (float)k * p, &s, &c);
        float vr = c * invSqN, vi = s * invSqN;
        g_Vxr[idx] = vr; g_Vxi[idx] = vi;
        g_Vxnr[n * KM + k] = vr; g_Vxni[n * KM + k] = vi;
    }
    for (int idx = t; idx < KM * MY; idx += stride) {
        int k = idx / MY, m = idx % MY;
        float p = (sy[m] - y0) * invRY;
        float s, c; sincosf(-TWO_PI * (float)k * p, &s, &c);
        float vr = c * invSqM, vi = s * invSqM;
        g_Vyr[idx] = vr; g_Vyi[idx] = vi;
        g_Vymr[m * KM + k] = vr; g_Vymi[m * KM + k] = vi;
    }
    for (int n = t; n < NX; n += stride) g_gx[n] = (sx[n] - x0) / xL;
    for (int m = t; m < MY; m += stride) g_gy[m] = (sy[m] - y0) / yL;
}

// ---------------- fc0 ----------------
__global__ void fc0K(const float* __restrict__ x,
                     const float* __restrict__ w,
                     const float* __restrict__ bias) {
    __shared__ float sX[18][128];
    __shared__ float sW[18][32];
    __shared__ float sB[32];
    int tid = threadIdx.x;
    for (int idx = tid; idx < 18 * 32; idx += 256) sW[idx >> 5][idx & 31] = w[idx];
    if (tid < 32) sB[tid] = bias[tid];

    int p0 = blockIdx.x * 128;
    {
        int pp = tid & 127, hf = tid >> 7;
        int p = p0 + pp;
        const float4* xp = (const float4*)(x + (size_t)p * 16) + hf * 2;
        float4 a = xp[0], b4 = xp[1];
        int c0 = hf * 8;
        sX[c0 + 0][pp] = a.x;  sX[c0 + 1][pp] = a.y;
        sX[c0 + 2][pp] = a.z;  sX[c0 + 3][pp] = a.w;
        sX[c0 + 4][pp] = b4.x; sX[c0 + 5][pp] = b4.y;
        sX[c0 + 6][pp] = b4.z; sX[c0 + 7][pp] = b4.w;
        if (hf == 0) {
            int mn = p % PLANE;
            sX[16][pp] = g_gx[mn % NX];
            sX[17][pp] = g_gy[mn / NX];
        }
    }
    __syncthreads();

    int og = tid >> 5, pg = tid & 31;
    float t[4][4];
#pragma unroll
    for (int a = 0; a < 4; a++) {
        float bb = sB[og * 4 + a];
#pragma unroll
        for (int j = 0; j < 4; j++) t[a][j] = bb;
    }

#pragma unroll 2
    for (int c = 0; c < 18; c++) {
        float4 x4 = *(const float4*)&sX[c][pg * 4];
        float xv[4] = {x4.x, x4.y, x4.z, x4.w};
        float4 w4 = *(const float4*)&sW[c][og * 4];
        float wv[4] = {w4.x, w4.y, w4.z, w4.w};
#pragma unroll
        for (int a = 0; a < 4; a++)
#pragma unroll
            for (int j = 0; j < 4; j++) t[a][j] = fmaf(wv[a], xv[j], t[a][j]);
    }
#pragma unroll
    for (int a = 0; a < 4; a++) {
        int o = og * 4 + a;
#pragma unroll
        for (int j = 0; j < 4; j++) {
            int p = p0 + pg * 4 + j;
            int b = p / PLANE, mn = p % PLANE;
            g_h[((size_t)b * CW + o) * PLANE + mn] = t[a][j];
        }
    }
}

// ---------------- fused forward transforms (fty pipelined via cp.async) ----------------
__global__ void __launch_bounds__(256, 4) ftK() {
    int bi = blockIdx.y;
    int tid = threadIdx.x;
    const float* hb = g_h + (size_t)bi * PLANE;

    // union smem: fty needs 30720B, ftx needs 28224B
    __shared__ __align__(16) char sBuf[30720];

    if (blockIdx.x < 3) {
        // ---- fty: FTY[k][n] = sum_m Vy[k][m] * H[m][n], 9 chunks of 20 m, double buffered ----
        float4* sH  = (float4*)sBuf;            // [2][20][32]
        float4* sVr = (float4*)(sBuf + 20480);  // [2][20][8]
        float4* sVi = (float4*)(sBuf + 25600);  // [2][20][8]

        int n0 = blockIdx.x * 128;
        int kg = tid >> 5, ng = tid & 31;

        float cr[4][4], ci[4][4];
#pragma unroll
        for (int a = 0; a < 4; a++)
#pragma unroll
            for (int j = 0; j < 4; j++) { cr[a][j] = 0.f; ci[a][j] = 0.f; }

        // stage chunk 0
        {
            int m0 = 0;
            for (int idx = tid; idx < 640; idx += 256) {
                int mm = idx >> 5, n4 = idx & 31;
                int gn = n0 + n4 * 4;
                cpa16(&sH[idx], &hb[(m0 + mm) * NX + gn], (gn < NX) ? 16 : 0);
            }
            for (int idx = tid; idx < 160; idx += 256) {
                int mm = idx >> 3, k4 = idx & 7;
                cpa16(&sVr[idx], &g_Vymr[(m0 + mm) * KM + k4 * 4], 16);
                cpa16(&sVi[idx], &g_Vymi[(m0 + mm) * KM + k4 * 4], 16);
            }
            CPA_COMMIT();
        }

        for (int c = 0; c < 9; c++) {
            if (c < 8) {
                int m0 = (c + 1) * 20;
                int buf = (c + 1) & 1;
                for (int idx = tid; idx < 640; idx += 256) {
                    int mm = idx >> 5, n4 = idx & 31;
                    int gn = n0 + n4 * 4;
                    cpa16(&sH[buf * 640 + idx], &hb[(m0 + mm) * NX + gn], (gn < NX) ? 16 : 0);
                }
                for (int idx = tid; idx < 160; idx += 256) {
                    int mm = idx >> 3, k4 = idx & 7;
                    cpa16(&sVr[buf * 160 + idx], &g_Vymr[(m0 + mm) * KM + k4 * 4], 16);
                    cpa16(&sVi[buf * 160 + idx], &g_Vymi[(m0 + mm) * KM + k4 * 4], 16);
                }
                CPA_COMMIT();
                CPA_WAIT1();
            } else {
                CPA_WAIT0();
            }
            __syncthreads();

            int cur = c & 1;
#pragma unroll 5
            for (int mm = 0; mm < 20; mm++) {
                float4 h4 = sH[cur * 640 + mm * 32 + ng];
                float hv[4] = {h4.x, h4.y, h4.z, h4.w};
                float4 vr4 = sVr[cur * 160 + mm * 8 + kg];
                float4 vi4 = sVi[cur * 160 + mm * 8 + kg];
                float vr[4] = {vr4.x, vr4.y, vr4.z, vr4.w};
                float vi[4] = {vi4.x, vi4.y, vi4.z, vi4.w};
#pragma unroll
                for (int a = 0; a < 4; a++)
#pragma unroll
                    for (int j = 0; j < 4; j++) {
                        cr[a][j] = fmaf(vr[a], hv[j], cr[a][j]);
                        ci[a][j] = fmaf(vi[a], hv[j], ci[a][j]);
                    }
            }
            __syncthreads();
        }
        int n = n0 + ng * 4;
        if (n < NX) {
#pragma unroll
            for (int a = 0; a < 4; a++) {
                int k = kg * 4 + a;
                size_t off = ((size_t)bi * KM + k) * NX + n;
                *(float4*)&g_ftyr[off] = make_float4(cr[a][0], cr[a][1], cr[a][2], cr[a][3]);
                *(float4*)&g_ftyi[off] = make_float4(ci[a][0], ci[a][1], ci[a][2], ci[a][3]);
            }
        }
    } else {
        // ---- ftx: FTX[k][m] = sum_n Vx[k][n] * H[m][n] ----
        float4* sVr2 = (float4*)sBuf;            // [36][8]
        float4* sVi2 = (float4*)(sBuf + 4608);   // [36][8]
        float*  sHT  = (float*)(sBuf + 9216);    // [36][132]

        int m0 = (blockIdx.x - 3) * 128;
        int kg = tid >> 5, mg = tid & 31;

        float cr[4][4], ci[4][4];
#pragma unroll
        for (int a = 0; a < 4; a++)
#pragma unroll
            for (int j = 0; j < 4; j++) { cr[a][j] = 0.f; ci[a][j] = 0.f; }

        for (int n0 = 0; n0 < NX; n0 += 36) {
            for (int idx = tid; idx < 1152; idx += 256) {
                int m = idx / 9, q = idx % 9;
                int gm = m0 + m;
                float4 v = (gm < MY) ? *(const float4*)&hb[gm * NX + n0 + q * 4]
                                     : make_float4(0.f, 0.f, 0.f, 0.f);
                int nn = q * 4;
                sHT[nn * 132 + m] = v.x; sHT[(nn + 1) * 132 + m] = v.y;
                sHT[(nn + 2) * 132 + m] = v.z; sHT[(nn + 3) * 132 + m] = v.w;
            }
            for (int idx = tid; idx < 288; idx += 256) {
                int nn = idx >> 3, k4 = idx & 7;
                sVr2[nn * 8 + k4] = *(const float4*)&g_Vxnr[(n0 + nn) * KM + k4 * 4];
                sVi2[nn * 8 + k4] = *(const float4*)&g_Vxni[(n0 + nn) * KM + k4 * 4];
            }
            __syncthreads();
#pragma unroll 6
            for (int nn = 0; nn < 36; nn++) {
                float4 h4 = *(const float4*)&sHT[nn * 132 + mg * 4];
                float hv[4] = {h4.x, h4.y, h4.z, h4.w};
                float4 vr4 = sVr2[nn * 8 + kg];
                float4 vi4 = sVi2[nn * 8 + kg];
                float vr[4] = {vr4.x, vr4.y, vr4.z, vr4.w};
                float vi[4] = {vi4.x, vi4.y, vi4.z, vi4.w};
#pragma unroll
                for (int a = 0; a < 4; a++)
#pragma unroll
                    for (int j = 0; j < 4; j++) {
                        cr[a][j] = fmaf(vr[a], hv[j], cr[a][j]);
                        ci[a][j] = fmaf(vi[a], hv[j], ci[a][j]);
                    }
            }
            __syncthreads();
        }
        int m = m0 + mg * 4;
        if (m < MY) {
#pragma unroll
            for (int a = 0; a < 4; a++) {
                int k = kg * 4 + a;
                size_t off = ((size_t)bi * KM + k) * MY + m;
                *(float4*)&g_ftxr[off] = make_float4(cr[a][0], cr[a][1], cr[a][2], cr[a][3]);
                *(float4*)&g_ftxi[off] = make_float4(ci[a][0], ci[a][1], ci[a][2], ci[a][3]);
            }
        }
    }
}

// ---------------- fused mode mix (two-phase cp.async overlap) ----------------
__global__ void __launch_bounds__(256, 4) mixFK(const float* __restrict__ fw1,
                                                const float* __restrict__ fw2) {
    int isY = (blockIdx.x < 3);
    const float* fw = isY ? fw1 : fw2;
    const float* finr = isY ? g_ftyr : g_ftxr;
    const float* fini = isY ? g_ftyi : g_ftxi;
    float* foutr = isY ? g_oyr : g_oxr;
    float* fouti = isY ? g_oyi : g_oxi;
    int L = isY ? NX : MY;
    int l0 = (isY ? blockIdx.x : (blockIdx.x - 3)) * 128;

    int b = blockIdx.z, k = blockIdx.y;
    int tid = threadIdx.x;
    int og = tid >> 5, lg = tid & 31;

    __shared__ float  sWr[32][32], sWi[32][32];
    __shared__ float4 sFr[32][32], sFi[32][32];

    // phase A: i = 0..15 via cp.async
    for (int idx = tid; idx < 512; idx += 256) {
        int i = idx >> 5, l4 = idx & 31;
        int gl = l0 + l4 * 4;
        size_t off = ((size_t)(b * CW + i) * KM + k) * L + gl;
        int sz = (gl < L) ? 16 : 0;
        cpa16(&sFr[i][l4], &finr[off], sz);
        cpa16(&sFi[i][l4], &fini[off], sz);
    }
    CPA_COMMIT();
    // phase B: i = 16..31 via cp.async
    for (int idx = 512 + tid; idx < 1024; idx += 256) {
        int i = idx >> 5, l4 = idx & 31;
        int gl = l0 + l4 * 4;
        size_t off = ((size_t)(b * CW + i) * KM + k) * L + gl;
        int sz = (gl < L) ? 16 : 0;
        cpa16(&sFr[i][l4], &finr[off], sz);
        cpa16(&sFi[i][l4], &fini[off], sz);
    }
    CPA_COMMIT();
    // weights via regular loads (covered by the barrier below)
    for (int idx = tid; idx < 1024; idx += 256) {
        int i = idx >> 5, o = idx & 31;
        const float* p = fw + ((size_t)(i * 32 + o) * KM + k) * 2;
        sWr[i][o] = p[0]; sWi[i][o] = p[1];
    }

    float cr[4][4], ci[4][4];
#pragma unroll
    for (int a = 0; a < 4; a++)
#pragma unroll
        for (int j = 0; j < 4; j++) { cr[a][j] = 0.f; ci[a][j] = 0.f; }

    CPA_WAIT1();
    __syncthreads();

#pragma unroll 4
    for (int i = 0; i < 16; i++) {
        float4 fr4 = sFr[i][lg], fi4 = sFi[i][lg];
        float fr[4] = {fr4.x, fr4.y, fr4.z, fr4.w};
        float fi[4] = {fi4.x, fi4.y, fi4.z, fi4.w};
        float4 wr4 = *(const float4*)&sWr[i][og * 4];
        float4 wi4 = *(const float4*)&sWi[i][og * 4];
        float wr[4] = {wr4.x, wr4.y, wr4.z, wr4.w};
        float wi[4] = {wi4.x, wi4.y, wi4.z, wi4.w};
#pragma unroll
        for (int a = 0; a < 4; a++) {
            float wrv = wr[a], wiv = wi[a];
#pragma unroll
            for (int j = 0; j < 4; j++) {
                cr[a][j] = fmaf(wrv, fr[j], cr[a][j]);
                cr[a][j] = fmaf(-wiv, fi[j], cr[a][j]);
                ci[a][j] = fmaf(wrv, fi[j], ci[a][j]);
                ci[a][j] = fmaf(wiv, fr[j], ci[a][j]);
            }
        }
    }

    CPA_WAIT0();
    __syncthreads();

#pragma unroll 4
    for (int i = 16; i < 32; i++) {
        float4 fr4 = sFr[i][lg], fi4 = sFi[i][lg];
        float fr[4] = {fr4.x, fr4.y, fr4.z, fr4.w};
        float fi[4] = {fi4.x, fi4.y, fi4.z, fi4.w};
        float4 wr4 = *(const float4*)&sWr[i][og * 4];
        float4 wi4 = *(const float4*)&sWi[i][og * 4];
        float wr[4] = {wr4.x, wr4.y, wr4.z, wr4.w};
        float wi[4] = {wi4.x, wi4.y, wi4.z, wi4.w};
#pragma unroll
        for (int a = 0; a < 4; a++) {
            float wrv = wr[a], wiv = wi[a];
#pragma unroll
            for (int j = 0; j < 4; j++) {
                cr[a][j] = fmaf(wrv, fr[j], cr[a][j]);
                cr[a][j] = fmaf(-wiv, fi[j], cr[a][j]);
                ci[a][j] = fmaf(wrv, fi[j], ci[a][j]);
                ci[a][j] = fmaf(wiv, fr[j], ci[a][j]);
            }
        }
    }

    int gl = l0 + lg * 4;
    if (gl < L) {
#pragma unroll
        for (int a = 0; a < 4; a++) {
            int o = og * 4 + a;
            size_t off = ((size_t)(b * CW + o) * KM + k) * L + gl;
            *(float4*)&foutr[off] = make_float4(cr[a][0], cr[a][1], cr[a][2], cr[a][3]);
            *(float4*)&fouti[off] = make_float4(ci[a][0], ci[a][1], ci[a][2], ci[a][3]);
        }
    }
}

// ---------------- fused inverse: x1 = invY + invX, 4 k-chunks of 8, double buffered ----------------
__global__ void __launch_bounds__(256, 4) invK() {
    int bo = blockIdx.z;
    int m0 = blockIdx.y * 64;
    int n0 = blockIdx.x * 64;
    int tid = threadIdx.x;
    int mg = tid >> 4, ng = tid & 15;
    int mlim = (m0 == 128) ? 13 : 16;
    int nlim = (n0 == 320) ? 10 : 16;

    // 8 arrays x [2 buf][8 k][16 q] float4 = 32KB
    __shared__ float4 sVyr[2][8][16], sVyi[2][8][16], sOxr[2][8][16], sOxi[2][8][16];
    __shared__ float4 sOyr[2][8][16], sOyi[2][8][16], sVxr[2][8][16], sVxi[2][8][16];

    float acc[4][4];
#pragma unroll
    for (int a = 0; a < 4; a++)
#pragma unroll
        for (int j = 0; j < 4; j++) acc[a][j] = 0.f;

    // stage chunk 0
    if (tid < 128) {
        int kk = tid >> 4, q = tid & 15;
        int kabs = kk;
        int msz = (q < mlim) ? 16 : 0;
        int nsz = (q < nlim) ? 16 : 0;
        size_t obY = ((size_t)bo * KM + kabs) * NX + n0 + q * 4;
        size_t obX = ((size_t)bo * KM + kabs) * MY + m0 + q * 4;
        cpa16(&sVyr[0][kk][q], &g_Vyr[kabs * MY + m0 + q * 4], msz);
        cpa16(&sVyi[0][kk][q], &g_Vyi[kabs * MY + m0 + q * 4], msz);
        cpa16(&sOxr[0][kk][q], &g_oxr[obX], msz);
        cpa16(&sOxi[0][kk][q], &g_oxi[obX], msz);
        cpa16(&sOyr[0][kk][q], &g_oyr[obY], nsz);
        cpa16(&sOyi[0][kk][q], &g_oyi[obY], nsz);
        cpa16(&sVxr[0][kk][q], &g_Vxr[kabs * NX + n0 + q * 4], nsz);
        cpa16(&sVxi[0][kk][q], &g_Vxi[kabs * NX + n0 + q * 4], nsz);
    }
    CPA_COMMIT();

    for (int c = 0; c < 4; c++) {
        if (c < 3) {
            int buf = (c + 1) & 1;
            if (tid < 128) {
                int kk = tid >> 4, q = tid & 15;
                int kabs = (c + 1) * 8 + kk;
                int msz = (q < mlim) ? 16 : 0;
                int nsz = (q < nlim) ? 16 : 0;
                size_t obY = ((size_t)bo * KM + kabs) * NX + n0 + q * 4;
                size_t obX = ((size_t)bo * KM + kabs) * MY + m0 + q * 4;
                cpa16(&sVyr[buf][kk][q], &g_Vyr[kabs * MY + m0 + q * 4], msz);
                cpa16(&sVyi[buf][kk][q], &g_Vyi[kabs * MY + m0 + q * 4], msz);
                cpa16(&sOxr[buf][kk][q], &g_oxr[obX], msz);
                cpa16(&sOxi[buf][kk][q], &g_oxi[obX], msz);
                cpa16(&sOyr[buf][kk][q], &g_oyr[obY], nsz);
                cpa16(&sOyi[buf][kk][q], &g_oyi[obY], nsz);
                cpa16(&sVxr[buf][kk][q], &g_Vxr[kabs * NX + n0 + q * 4], nsz);
                cpa16(&sVxi[buf][kk][q], &g_Vxi[kabs * NX + n0 + q * 4], nsz);
            }
            CPA_COMMIT();
            CPA_WAIT1();
        } else {
            CPA_WAIT0();
        }
        __syncthreads();

        int cur = c & 1;
#pragma unroll
        for (int j = 0; j < 8; j++) {
            float4 vyr4 = sVyr[cur][j][mg], vyi4 = sVyi[cur][j][mg];
            float4 oxr4 = sOxr[cur][j][mg], oxi4 = sOxi[cur][j][mg];
            float4 oyr4 = sOyr[cur][j][ng], oyi4 = sOyi[cur][j][ng];
            float4 vxr4 = sVxr[cur][j][ng], vxi4 = sVxi[cur][j][ng];
            float vyr[4] = {vyr4.x, vyr4.y, vyr4.z, vyr4.w};
            float vyi[4] = {vyi4.x, vyi4.y, vyi4.z, vyi4.w};
            float oxr[4] = {oxr4.x, oxr4.y, oxr4.z, oxr4.w};
            float oxi[4] = {oxi4.x, oxi4.y, oxi4.z, oxi4.w};
            float oyr[4] = {oyr4.x, oyr4.y, oyr4.z, oyr4.w};
            float oyi[4] = {oyi4.x, oyi4.y, oyi4.z, oyi4.w};
            float vxr[4] = {vxr4.x, vxr4.y, vxr4.z, vxr4.w};
            float vxi[4] = {vxi4.x, vxi4.y, vxi4.z, vxi4.w};
#pragma unroll
            for (int a = 0; a < 4; a++)
#pragma unroll
                for (int q2 = 0; q2 < 4; q2++) {
                    float s = acc[a][q2];
                    s = fmaf(vyr[a], oyr[q2], s);
                    s = fmaf(vyi[a], oyi[q2], s);
                    s = fmaf(oxr[a], vxr[q2], s);
                    s = fmaf(oxi[a], vxi[q2], s);
                    acc[a][q2] = s;
                }
        }
        __syncthreads();
    }

    if (ng < nlim && mg < mlim) {
        float* xb = g_x1 + (size_t)bo * PLANE;
        int n = n0 + ng * 4;
#pragma unroll
        for (int a = 0; a < 4; a++) {
            int m = m0 + mg * 4 + a;
            *(float4*)&xb[m * NX + n] =
                make_float4(acc[a][0], acc[a][1], acc[a][2], acc[a][3]);
        }
    }
}

// ---------------- pointwise MLP + residual ----------------
__global__ void __launch_bounds__(256, 4) pwK(const float* __restrict__ w1, const float* __restrict__ b1,
                    const float* __restrict__ w2, const float* __restrict__ b2,
                    int applyGelu) {
    __shared__ float sX[32][128];
    __shared__ float sT[32][132];
    __shared__ float sW1[32][32], sW2[32][32];
    __shared__ float sB1[32], sB2[32];
    int tid = threadIdx.x;
    for (int idx = tid; idx < 1024; idx += 256) {
        int o = idx >> 5, c = idx & 31;
        sW1[c][o] = w1[o * 32 + c];
        sW2[c][o] = w2[o * 32 + c];
    }
    if (tid < 32) { sB1[tid] = b1[tid]; sB2[tid] = b2[tid]; }

    int p0 = blockIdx.x * 128;
    {
        int pp = tid & 127, ch = (tid >> 7) * 16;
        int p = p0 + pp;
        int b = p / PLANE, mn = p % PLANE;
        const float* src = g_x1 + ((size_t)b * CW + ch) * PLANE + mn;
#pragma unroll
        for (int cc = 0; cc < 16; cc++) sX[ch + cc][pp] = src[(size_t)cc * PLANE];
    }
    __syncthreads();

    int og = tid >> 5, pg = tid & 31;
    {
        float t[4][4];
#pragma unroll
        for (int a = 0; a < 4; a++) {
            float bb = sB1[og * 4 + a];
#pragma unroll
            for (int j = 0; j < 4; j++) t[a][j] = bb;
        }
#pragma unroll 4
        for (int c = 0; c < 32; c++) {
            float4 x4 = *(const float4*)&sX[c][pg * 4];
            float xv[4] = {x4.x, x4.y, x4.z, x4.w};
            float4 w4 = *(const float4*)&sW1[c][og * 4];
            float wv[4] = {w4.x, w4.y, w4.z, w4.w};
#pragma unroll
            for (int a = 0; a < 4; a++)
#pragma unroll
                for (int j = 0; j < 4; j++) t[a][j] = fmaf(wv[a], xv[j], t[a][j]);
        }
#pragma unroll
        for (int a = 0; a < 4; a++)
            *(float4*)&sT[og * 4 + a][pg * 4] =
                make_float4(geluf(t[a][0]), geluf(t[a][1]), geluf(t[a][2]), geluf(t[a][3]));
    }
    __syncthreads();
    {
        float t[4][4];
#pragma unroll
        for (int a = 0; a < 4; a++) {
            float bb = sB2[og * 4 + a];
#pragma unroll
            for (int j = 0; j < 4; j++) t[a][j] = bb;
        }
#pragma unroll 4
        for (int c = 0; c < 32; c++) {
            float4 x4 = *(const float4*)&sT[c][pg * 4];
            float xv[4] = {x4.x, x4.y, x4.z, x4.w};
            float4 w4 = *(const float4*)&sW2[c][og * 4];
            float wv[4] = {w4.x, w4.y, w4.z, w4.w};
#pragma unroll
            for (int a = 0; a < 4; a++)
#pragma unroll
                for (int j = 0; j < 4; j++) t[a][j] = fmaf(wv[a], xv[j], t[a][j]);
        }
        int pbase = p0 + pg * 4;
#pragma unroll
        for (int a = 0; a < 4; a++) {
            int o = og * 4 + a;
#pragma unroll
            for (int j = 0; j < 4; j++) {
                int p = pbase + j;
                int b = p / PLANE, mn = p % PLANE;
                size_t off = ((size_t)b * CW + o) * PLANE + mn;
                float s = t[a][j];
                if (applyGelu) s = geluf(s);
                g_h[off] += s;
            }
        }
    }
}

// ---------------- final head ----------------
__global__ void __launch_bounds__(256, 4) finalK(const float* __restrict__ fc1w, const float* __restrict__ fc1b,
                       const float* __restrict__ fc2w, const float* __restrict__ fc2b,
                       float* __restrict__ out) {
    __shared__ float sX[32][68];
    __shared__ float sW1h[32][64];
    __shared__ float sT[64][68];
    __shared__ float sw2[128], sb1[128];
    __shared__ float sRed[4][64];
    int tid = threadIdx.x;
    if (tid < 128) { sw2[tid] = fc2w[tid]; sb1[tid] = fc1b[tid]; }

    int p0 = blockIdx.x * 64;
    {
        int pp = tid & 63, ch = (tid >> 6) * 8;
        int p = p0 + pp;
        int b = p / PLANE, mn = p % PLANE;
        const float* src = g_h + ((size_t)b * CW + ch) * PLANE + mn;
#pragma unroll
        for (int cc = 0; cc < 8; cc++) sX[ch + cc][pp] = src[(size_t)cc * PLANE];
    }

    float part = 0.f;
    for (int jh = 0; jh < 128; jh += 64) {
        __syncthreads();
        for (int idx = tid; idx < 512; idx += 256) {
            int c = idx >> 4, j4 = idx & 15;
            *(float4*)&sW1h[c][j4 * 4] = *(const float4*)&fc1w[c * 128 + jh + j4 * 4];
        }
        __syncthreads();

        int jg = tid >> 4, pgr = tid & 15;
        float t[4][4];
#pragma unroll
        for (int a = 0; a < 4; a++) {
            float bb = sb1[jh + jg * 4 + a];
#pragma unroll
            for (int j = 0; j < 4; j++) t[a][j] = bb;
        }
#pragma unroll 4
        for (int c = 0; c < 32; c++) {
            float4 x4 = *(const float4*)&sX[c][pgr * 4];
            float xv[4] = {x4.x, x4.y, x4.z, x4.w};
            float4 w4 = *(const float4*)&sW1h[c][jg * 4];
            float wv[4] = {w4.x, w4.y, w4.z, w4.w};
#pragma unroll
            for (int a = 0; a < 4; a++)
#pragma unroll
                for (int j = 0; j < 4; j++) t[a][j] = fmaf(wv[a], xv[j], t[a][j]);
        }
#pragma unroll
        for (int a = 0; a < 4; a++)
            *(float4*)&sT[jg * 4 + a][pgr * 4] =
                make_float4(geluf(t[a][0]), geluf(t[a][1]), geluf(t[a][2]), geluf(t[a][3]));
        __syncthreads();
        {
            int pq = tid & 63, jq = tid >> 6;
            float s = 0.f;
#pragma unroll
            for (int jj = 0; jj < 16; jj++) {
                int j = jq * 16 + jj;
                s = fmaf(sw2[jh + j], sT[j][pq], s);
            }
            part += s;
        }
    }
    __syncthreads();
    {
        int pq = tid & 63, jq = tid >> 6;
        sRed[jq][pq] = part;
    }
    __syncthreads();
    if (tid < 64) {
        out[p0 + tid] = sRed[0][tid] + sRed[1][tid] + sRed[2][tid] + sRed[3][tid] + fc2b[0];
    }
}

// ---------------- launch ----------------
extern "C" void kernel_launch(void* const* d_in, const int* in_sizes, int n_in,
                              void* d_out, int out_size) {
    (void)in_sizes; (void)n_in; (void)out_size;
    const float* x    = (const float*)d_in[0];
    const float* sx   = (const float*)d_in[1];
    const float* sy   = (const float*)d_in[2];
    const float* fc0w = (const float*)d_in[3];
    const float* fc0b = (const float*)d_in[4];
    const float* fw1  = (const float*)d_in[5];
    const float* fw2  = (const float*)d_in[6];
    const float* w1   = (const float*)d_in[7];
    const float* b1   = (const float*)d_in[8];
    const float* w2   = (const float*)d_in[9];
    const float* b2   = (const float*)d_in[10];
    const float* fc1w = (const float*)d_in[11];
    const float* fc1b = (const float*)d_in[12];
    const float* fc2w = (const float*)d_in[13];
    const float* fc2b = (const float*)d_in[14];
    float* out = (float*)d_out;

    precomputeK<<<64, 256>>>(sx, sy);
    fc0K<<<PIX / 128, 256>>>(x, fc0w, fc0b);

    for (int blk = 0; blk < 4; blk++) {
        const float* fw1p = fw1 + (size_t)blk * CW * CW * KM * 2;
        const float* fw2p = fw2 + (size_t)blk * CW * CW * KM * 2;
        const float* w1p  = w1 + (size_t)blk * CW * CW;
        const float* b1p  = b1 + (size_t)blk * CW;
        const float* w2p  = w2 + (size_t)blk * CW * CW;
        const float* b2p  = b2 + (size_t)blk * CW;

        ftK<<<dim3(5, BSZ * CW), 256>>>();
        mixFK<<<dim3(5, KM, BSZ), 256>>>(fw1p, fw2p);
        invK<<<dim3(6, 3, BSZ * CW), 256>>>();
        pwK<<<PIX / 128, 256>>>(w1p, b1p, w2p, b2p, blk < 3 ? 1 : 0);
    }

    finalK<<<PIX / 64, 256>>>(fc1w, fc1b, fc2w, fc2b, out);
}

// round 10
// speedup vs baseline: 1.1019x; 1.1019x over previous
#include <cuda_runtime.h>
#include <math.h>

#define BSZ 16
#define CW  32
#define MY  180
#define NX  360
#define KM  32
#define PLANE (MY*NX)
#define PIX (BSZ*PLANE)

__device__ __forceinline__ float geluf(float x) {
    return 0.5f * x * (1.0f + erff(x * 0.70710678118654752f));
}

__device__ __forceinline__ void cpa16(void* dst, const void* src, int szbytes) {
    unsigned d = (unsigned)__cvta_generic_to_shared(dst);
    asm volatile("cp.async.cg.shared.global [%0], [%1], 16, %2;"
                 :: "r"(d), "l"(src), "r"(szbytes) : "memory");
}
__device__ __forceinline__ void cpa4(void* dst, const void* src) {
    unsigned d = (unsigned)__cvta_generic_to_shared(dst);
    asm volatile("cp.async.ca.shared.global [%0], [%1], 4;"
                 :: "r"(d), "l"(src) : "memory");
}
#define CPA_COMMIT() asm volatile("cp.async.commit_group;" ::: "memory")
#define CPA_WAIT0()  asm volatile("cp.async.wait_group 0;" ::: "memory")
#define CPA_WAIT1()  asm volatile("cp.async.wait_group 1;" ::: "memory")

// ---------------- device scratch ----------------
__device__ __align__(16) float g_h  [BSZ*CW*PLANE];
__device__ __align__(16) float g_x1 [BSZ*CW*PLANE];
__device__ __align__(16) float g_ftyr[BSZ*CW*KM*NX];
__device__ __align__(16) float g_ftyi[BSZ*CW*KM*NX];
__device__ __align__(16) float g_oyr [BSZ*CW*KM*NX];
__device__ __align__(16) float g_oyi [BSZ*CW*KM*NX];
__device__ __align__(16) float g_ftxr[BSZ*CW*KM*MY];
__device__ __align__(16) float g_ftxi[BSZ*CW*KM*MY];
__device__ __align__(16) float g_oxr [BSZ*CW*KM*MY];
__device__ __align__(16) float g_oxi [BSZ*CW*KM*MY];
__device__ __align__(16) float g_Vyr [KM*MY], g_Vyi [KM*MY];   // [k][m]
__device__ __align__(16) float g_Vymr[MY*KM], g_Vymi[MY*KM];   // [m][k]
__device__ __align__(16) float g_Vxr [KM*NX], g_Vxi [KM*NX];   // [k][n]
__device__ __align__(16) float g_Vxnr[NX*KM], g_Vxni[NX*KM];   // [n][k]
__device__ float g_gx[NX], g_gy[MY];

// ---------------- precompute ----------------
__global__ void precomputeK(const float* __restrict__ sx,
                            const float* __restrict__ sy) {
    int t = blockIdx.x * blockDim.x + threadIdx.x;
    int stride = gridDim.x * blockDim.x;
    float x0 = sx[0], xL = sx[NX - 1];
    float y0 = sy[0], yL = sy[MY - 1];
    float invRX = 1.0f / (xL - x0), invRY = 1.0f / (yL - y0);
    float invSqN = rsqrtf((float)NX), invSqM = rsqrtf((float)MY);
    const float TWO_PI = 6.283185307179586f;

    for (int idx = t; idx < KM * NX; idx += stride) {
        int k = idx / NX, n = idx % NX;
        float p = (sx[n] - x0) * invRX;
        float s, c; sincosf(-TWO_PI * (float)k * p, &s, &c);
        float vr = c * invSqN, vi = s * invSqN;
        g_Vxr[idx] = vr; g_Vxi[idx] = vi;
        g_Vxnr[n * KM + k] = vr; g_Vxni[n * KM + k] = vi;
    }
    for (int idx = t; idx < KM * MY; idx += stride) {
        int k = idx / MY, m = idx % MY;
        float p = (sy[m] - y0) * invRY;
        float s, c; sincosf(-TWO_PI * (float)k * p, &s, &c);
        float vr = c * invSqM, vi = s * invSqM;
        g_Vyr[idx] = vr; g_Vyi[idx] = vi;
        g_Vymr[m * KM + k] = vr; g_Vymi[m * KM + k] = vi;
    }
    for (int n = t; n < NX; n += stride) g_gx[n] = (sx[n] - x0) / xL;
    for (int m = t; m < MY; m += stride) g_gy[m] = (sy[m] - y0) / yL;
}

// ---------------- fc0 ----------------
__global__ void fc0K(const float* __restrict__ x,
                     const float* __restrict__ w,
                     const float* __restrict__ bias) {
    __shared__ float sX[18][128];
    __shared__ float sW[18][32];
    __shared__ float sB[32];
    int tid = threadIdx.x;
    for (int idx = tid; idx < 18 * 32; idx += 256) sW[idx >> 5][idx & 31] = w[idx];
    if (tid < 32) sB[tid] = bias[tid];

    int p0 = blockIdx.x * 128;
    {
        int pp = tid & 127, hf = tid >> 7;
        int p = p0 + pp;
        const float4* xp = (const float4*)(x + (size_t)p * 16) + hf * 2;
        float4 a = xp[0], b4 = xp[1];
        int c0 = hf * 8;
        sX[c0 + 0][pp] = a.x;  sX[c0 + 1][pp] = a.y;
        sX[c0 + 2][pp] = a.z;  sX[c0 + 3][pp] = a.w;
        sX[c0 + 4][pp] = b4.x; sX[c0 + 5][pp] = b4.y;
        sX[c0 + 6][pp] = b4.z; sX[c0 + 7][pp] = b4.w;
        if (hf == 0) {
            int mn = p % PLANE;
            sX[16][pp] = g_gx[mn % NX];
            sX[17][pp] = g_gy[mn / NX];
        }
    }
    __syncthreads();

    int og = tid >> 5, pg = tid & 31;
    float t[4][4];
#pragma unroll
    for (int a = 0; a < 4; a++) {
        float bb = sB[og * 4 + a];
#pragma unroll
        for (int j = 0; j < 4; j++) t[a][j] = bb;
    }

#pragma unroll 2
    for (int c = 0; c < 18; c++) {
        float4 x4 = *(const float4*)&sX[c][pg * 4];
        float xv[4] = {x4.x, x4.y, x4.z, x4.w};
        float4 w4 = *(const float4*)&sW[c][og * 4];
        float wv[4] = {w4.x, w4.y, w4.z, w4.w};
#pragma unroll
        for (int a = 0; a < 4; a++)
#pragma unroll
            for (int j = 0; j < 4; j++) t[a][j] = fmaf(wv[a], xv[j], t[a][j]);
    }
#pragma unroll
    for (int a = 0; a < 4; a++) {
        int o = og * 4 + a;
#pragma unroll
        for (int j = 0; j < 4; j++) {
            int p = p0 + pg * 4 + j;
            int b = p / PLANE, mn = p % PLANE;
            g_h[((size_t)b * CW + o) * PLANE + mn] = t[a][j];
        }
    }
}

// ---------------- fused forward transforms (fty pipelined via cp.async) ----------------
__global__ void __launch_bounds__(256) ftK() {
    int bi = blockIdx.y;
    int tid = threadIdx.x;
    const float* hb = g_h + (size_t)bi * PLANE;

    // union smem: fty needs 30720B, ftx needs 28224B
    __shared__ __align__(16) char sBuf[30720];

    if (blockIdx.x < 3) {
        // ---- fty: FTY[k][n] = sum_m Vy[k][m] * H[m][n], 9 chunks of 20 m, double buffered ----
        float4* sH  = (float4*)sBuf;            // [2][20][32]
        float4* sVr = (float4*)(sBuf + 20480);  // [2][20][8]
        float4* sVi = (float4*)(sBuf + 25600);  // [2][20][8]

        int n0 = blockIdx.x * 128;
        int kg = tid >> 5, ng = tid & 31;

        float cr[4][4], ci[4][4];
#pragma unroll
        for (int a = 0; a < 4; a++)
#pragma unroll
            for (int j = 0; j < 4; j++) { cr[a][j] = 0.f; ci[a][j] = 0.f; }

        // stage chunk 0
        {
            int m0 = 0;
            for (int idx = tid; idx < 640; idx += 256) {
                int mm = idx >> 5, n4 = idx & 31;
                int gn = n0 + n4 * 4;
                cpa16(&sH[idx], &hb[(m0 + mm) * NX + gn], (gn < NX) ? 16 : 0);
            }
            for (int idx = tid; idx < 160; idx += 256) {
                int mm = idx >> 3, k4 = idx & 7;
                cpa16(&sVr[idx], &g_Vymr[(m0 + mm) * KM + k4 * 4], 16);
                cpa16(&sVi[idx], &g_Vymi[(m0 + mm) * KM + k4 * 4], 16);
            }
            CPA_COMMIT();
        }

        for (int c = 0; c < 9; c++) {
            if (c < 8) {
                int m0 = (c + 1) * 20;
                int buf = (c + 1) & 1;
                for (int idx = tid; idx < 640; idx += 256) {
                    int mm = idx >> 5, n4 = idx & 31;
                    int gn = n0 + n4 * 4;
                    cpa16(&sH[buf * 640 + idx], &hb[(m0 + mm) * NX + gn], (gn < NX) ? 16 : 0);
                }
                for (int idx = tid; idx < 160; idx += 256) {
                    int mm = idx >> 3, k4 = idx & 7;
                    cpa16(&sVr[buf * 160 + idx], &g_Vymr[(m0 + mm) * KM + k4 * 4], 16);
                    cpa16(&sVi[buf * 160 + idx], &g_Vymi[(m0 + mm) * KM + k4 * 4], 16);
                }
                CPA_COMMIT();
                CPA_WAIT1();
            } else {
                CPA_WAIT0();
            }
            __syncthreads();

            int cur = c & 1;
#pragma unroll 5
            for (int mm = 0; mm < 20; mm++) {
                float4 h4 = sH[cur * 640 + mm * 32 + ng];
                float hv[4] = {h4.x, h4.y, h4.z, h4.w};
                float4 vr4 = sVr[cur * 160 + mm * 8 + kg];
                float4 vi4 = sVi[cur * 160 + mm * 8 + kg];
                float vr[4] = {vr4.x, vr4.y, vr4.z, vr4.w};
                float vi[4] = {vi4.x, vi4.y, vi4.z, vi4.w};
#pragma unroll
                for (int a = 0; a < 4; a++)
#pragma unroll
                    for (int j = 0; j < 4; j++) {
                        cr[a][j] = fmaf(vr[a], hv[j], cr[a][j]);
                        ci[a][j] = fmaf(vi[a], hv[j], ci[a][j]);
                    }
            }
            __syncthreads();
        }
        int n = n0 + ng * 4;
        if (n < NX) {
#pragma unroll
            for (int a = 0; a < 4; a++) {
                int k = kg * 4 + a;
                size_t off = ((size_t)bi * KM + k) * NX + n;
                *(float4*)&g_ftyr[off] = make_float4(cr[a][0], cr[a][1], cr[a][2], cr[a][3]);
                *(float4*)&g_ftyi[off] = make_float4(ci[a][0], ci[a][1], ci[a][2], ci[a][3]);
            }
        }
    } else {
        // ---- ftx: FTX[k][m] = sum_n Vx[k][n] * H[m][n] ----
        float4* sVr2 = (float4*)sBuf;            // [36][8]
        float4* sVi2 = (float4*)(sBuf + 4608);   // [36][8]
        float*  sHT  = (float*)(sBuf + 9216);    // [36][132]

        int m0 = (blockIdx.x - 3) * 128;
        int kg = tid >> 5, mg = tid & 31;

        float cr[4][4], ci[4][4];
#pragma unroll
        for (int a = 0; a < 4; a++)
#pragma unroll
            for (int j = 0; j < 4; j++) { cr[a][j] = 0.f; ci[a][j] = 0.f; }

        for (int n0 = 0; n0 < NX; n0 += 36) {
            for (int idx = tid; idx < 1152; idx += 256) {
                int m = idx / 9, q = idx % 9;
                int gm = m0 + m;
                float4 v = (gm < MY) ? *(const float4*)&hb[gm * NX + n0 + q * 4]
                                     : make_float4(0.f, 0.f, 0.f, 0.f);
                int nn = q * 4;
                sHT[nn * 132 + m] = v.x; sHT[(nn + 1) * 132 + m] = v.y;
                sHT[(nn + 2) * 132 + m] = v.z; sHT[(nn + 3) * 132 + m] = v.w;
            }
            for (int idx = tid; idx < 288; idx += 256) {
                int nn = idx >> 3, k4 = idx & 7;
                sVr2[nn * 8 + k4] = *(const float4*)&g_Vxnr[(n0 + nn) * KM + k4 * 4];
                sVi2[nn * 8 + k4] = *(const float4*)&g_Vxni[(n0 + nn) * KM + k4 * 4];
            }
            __syncthreads();
#pragma unroll 6
            for (int nn = 0; nn < 36; nn++) {
                float4 h4 = *(const float4*)&sHT[nn * 132 + mg * 4];
                float hv[4] = {h4.x, h4.y, h4.z, h4.w};
                float4 vr4 = sVr2[nn * 8 + kg];
                float4 vi4 = sVi2[nn * 8 + kg];
                float vr[4] = {vr4.x, vr4.y, vr4.z, vr4.w};
                float vi[4] = {vi4.x, vi4.y, vi4.z, vi4.w};
#pragma unroll
                for (int a = 0; a < 4; a++)
#pragma unroll
                    for (int j = 0; j < 4; j++) {
                        cr[a][j] = fmaf(vr[a], hv[j], cr[a][j]);
                        ci[a][j] = fmaf(vi[a], hv[j], ci[a][j]);
                    }
            }
            __syncthreads();
        }
        int m = m0 + mg * 4;
        if (m < MY) {
#pragma unroll
            for (int a = 0; a < 4; a++) {
                int k = kg * 4 + a;
                size_t off = ((size_t)bi * KM + k) * MY + m;
                *(float4*)&g_ftxr[off] = make_float4(cr[a][0], cr[a][1], cr[a][2], cr[a][3]);
                *(float4*)&g_ftxi[off] = make_float4(ci[a][0], ci[a][1], ci[a][2], ci[a][3]);
            }
        }
    }
}

// ---------------- fused mode mix (two-phase cp.async overlap) ----------------
__global__ void __launch_bounds__(256) mixFK(const float* __restrict__ fw1,
                                             const float* __restrict__ fw2) {
    int isY = (blockIdx.x < 3);
    const float* fw = isY ? fw1 : fw2;
    const float* finr = isY ? g_ftyr : g_ftxr;
    const float* fini = isY ? g_ftyi : g_ftxi;
    float* foutr = isY ? g_oyr : g_oxr;
    float* fouti = isY ? g_oyi : g_oxi;
    int L = isY ? NX : MY;
    int l0 = (isY ? blockIdx.x : (blockIdx.x - 3)) * 128;

    int b = blockIdx.z, k = blockIdx.y;
    int tid = threadIdx.x;
    int og = tid >> 5, lg = tid & 31;

    __shared__ float  sWr[32][32], sWi[32][32];
    __shared__ float4 sFr[32][32], sFi[32][32];

    // phase A: i = 0..15 via cp.async
    for (int idx = tid; idx < 512; idx += 256) {
        int i = idx >> 5, l4 = idx & 31;
        int gl = l0 + l4 * 4;
        size_t off = ((size_t)(b * CW + i) * KM + k) * L + gl;
        int sz = (gl < L) ? 16 : 0;
        cpa16(&sFr[i][l4], &finr[off], sz);
        cpa16(&sFi[i][l4], &fini[off], sz);
    }
    CPA_COMMIT();
    // phase B: i = 16..31 via cp.async
    for (int idx = 512 + tid; idx < 1024; idx += 256) {
        int i = idx >> 5, l4 = idx & 31;
        int gl = l0 + l4 * 4;
        size_t off = ((size_t)(b * CW + i) * KM + k) * L + gl;
        int sz = (gl < L) ? 16 : 0;
        cpa16(&sFr[i][l4], &finr[off], sz);
        cpa16(&sFi[i][l4], &fini[off], sz);
    }
    CPA_COMMIT();
    // weights via regular loads (covered by the barrier below)
    for (int idx = tid; idx < 1024; idx += 256) {
        int i = idx >> 5, o = idx & 31;
        const float* p = fw + ((size_t)(i * 32 + o) * KM + k) * 2;
        sWr[i][o] = p[0]; sWi[i][o] = p[1];
    }

    float cr[4][4], ci[4][4];
#pragma unroll
    for (int a = 0; a < 4; a++)
#pragma unroll
        for (int j = 0; j < 4; j++) { cr[a][j] = 0.f; ci[a][j] = 0.f; }

    CPA_WAIT1();
    __syncthreads();

#pragma unroll 4
    for (int i = 0; i < 16; i++) {
        float4 fr4 = sFr[i][lg], fi4 = sFi[i][lg];
        float fr[4] = {fr4.x, fr4.y, fr4.z, fr4.w};
        float fi[4] = {fi4.x, fi4.y, fi4.z, fi4.w};
        float4 wr4 = *(const float4*)&sWr[i][og * 4];
        float4 wi4 = *(const float4*)&sWi[i][og * 4];
        float wr[4] = {wr4.x, wr4.y, wr4.z, wr4.w};
        float wi[4] = {wi4.x, wi4.y, wi4.z, wi4.w};
#pragma unroll
        for (int a = 0; a < 4; a++) {
            float wrv = wr[a], wiv = wi[a];
#pragma unroll
            for (int j = 0; j < 4; j++) {
                cr[a][j] = fmaf(wrv, fr[j], cr[a][j]);
                cr[a][j] = fmaf(-wiv, fi[j], cr[a][j]);
                ci[a][j] = fmaf(wrv, fi[j], ci[a][j]);
                ci[a][j] = fmaf(wiv, fr[j], ci[a][j]);
            }
        }
    }

    CPA_WAIT0();
    __syncthreads();

#pragma unroll 4
    for (int i = 16; i < 32; i++) {
        float4 fr4 = sFr[i][lg], fi4 = sFi[i][lg];
        float fr[4] = {fr4.x, fr4.y, fr4.z, fr4.w};
        float fi[4] = {fi4.x, fi4.y, fi4.z, fi4.w};
        float4 wr4 = *(const float4*)&sWr[i][og * 4];
        float4 wi4 = *(const float4*)&sWi[i][og * 4];
        float wr[4] = {wr4.x, wr4.y, wr4.z, wr4.w};
        float wi[4] = {wi4.x, wi4.y, wi4.z, wi4.w};
#pragma unroll
        for (int a = 0; a < 4; a++) {
            float wrv = wr[a], wiv = wi[a];
#pragma unroll
            for (int j = 0; j < 4; j++) {
                cr[a][j] = fmaf(wrv, fr[j], cr[a][j]);
                cr[a][j] = fmaf(-wiv, fi[j], cr[a][j]);
                ci[a][j] = fmaf(wrv, fi[j], ci[a][j]);
                ci[a][j] = fmaf(wiv, fr[j], ci[a][j]);
            }
        }
    }

    int gl = l0 + lg * 4;
    if (gl < L) {
#pragma unroll
        for (int a = 0; a < 4; a++) {
            int o = og * 4 + a;
            size_t off = ((size_t)(b * CW + o) * KM + k) * L + gl;
            *(float4*)&foutr[off] = make_float4(cr[a][0], cr[a][1], cr[a][2], cr[a][3]);
            *(float4*)&fouti[off] = make_float4(ci[a][0], ci[a][1], ci[a][2], ci[a][3]);
        }
    }
}

// ---------------- fused inverse: x1 = invY + invX, 4 k-chunks of 8, double buffered ----------------
__global__ void __launch_bounds__(256) invK() {
    int bo = blockIdx.z;
    int m0 = blockIdx.y * 64;
    int n0 = blockIdx.x * 64;
    int tid = threadIdx.x;
    int mg = tid >> 4, ng = tid & 15;
    int mlim = (m0 == 128) ? 13 : 16;
    int nlim = (n0 == 320) ? 10 : 16;

    // 8 arrays x [2 buf][8 k][16 q] float4 = 32KB
    __shared__ float4 sVyr[2][8][16], sVyi[2][8][16], sOxr[2][8][16], sOxi[2][8][16];
    __shared__ float4 sOyr[2][8][16], sOyi[2][8][16], sVxr[2][8][16], sVxi[2][8][16];

    float acc[4][4];
#pragma unroll
    for (int a = 0; a < 4; a++)
#pragma unroll
        for (int j = 0; j < 4; j++) acc[a][j] = 0.f;

    // stage chunk 0
    if (tid < 128) {
        int kk = tid >> 4, q = tid & 15;
        int kabs = kk;
        int msz = (q < mlim) ? 16 : 0;
        int nsz = (q < nlim) ? 16 : 0;
        size_t obY = ((size_t)bo * KM + kabs) * NX + n0 + q * 4;
        size_t obX = ((size_t)bo * KM + kabs) * MY + m0 + q * 4;
        cpa16(&sVyr[0][kk][q], &g_Vyr[kabs * MY + m0 + q * 4], msz);
        cpa16(&sVyi[0][kk][q], &g_Vyi[kabs * MY + m0 + q * 4], msz);
        cpa16(&sOxr[0][kk][q], &g_oxr[obX], msz);
        cpa16(&sOxi[0][kk][q], &g_oxi[obX], msz);
        cpa16(&sOyr[0][kk][q], &g_oyr[obY], nsz);
        cpa16(&sOyi[0][kk][q], &g_oyi[obY], nsz);
        cpa16(&sVxr[0][kk][q], &g_Vxr[kabs * NX + n0 + q * 4], nsz);
        cpa16(&sVxi[0][kk][q], &g_Vxi[kabs * NX + n0 + q * 4], nsz);
    }
    CPA_COMMIT();

    for (int c = 0; c < 4; c++) {
        if (c < 3) {
            int buf = (c + 1) & 1;
            if (tid < 128) {
                int kk = tid >> 4, q = tid & 15;
                int kabs = (c + 1) * 8 + kk;
                int msz = (q < mlim) ? 16 : 0;
                int nsz = (q < nlim) ? 16 : 0;
                size_t obY = ((size_t)bo * KM + kabs) * NX + n0 + q * 4;
                size_t obX = ((size_t)bo * KM + kabs) * MY + m0 + q * 4;
                cpa16(&sVyr[buf][kk][q], &g_Vyr[kabs * MY + m0 + q * 4], msz);
                cpa16(&sVyi[buf][kk][q], &g_Vyi[kabs * MY + m0 + q * 4], msz);
                cpa16(&sOxr[buf][kk][q], &g_oxr[obX], msz);
                cpa16(&sOxi[buf][kk][q], &g_oxi[obX], msz);
                cpa16(&sOyr[buf][kk][q], &g_oyr[obY], nsz);
                cpa16(&sOyi[buf][kk][q], &g_oyi[obY], nsz);
                cpa16(&sVxr[buf][kk][q], &g_Vxr[kabs * NX + n0 + q * 4], nsz);
                cpa16(&sVxi[buf][kk][q], &g_Vxi[kabs * NX + n0 + q * 4], nsz);
            }
            CPA_COMMIT();
            CPA_WAIT1();
        } else {
            CPA_WAIT0();
        }
        __syncthreads();

        int cur = c & 1;
#pragma unroll
        for (int j = 0; j < 8; j++) {
            float4 vyr4 = sVyr[cur][j][mg], vyi4 = sVyi[cur][j][mg];
            float4 oxr4 = sOxr[cur][j][mg], oxi4 = sOxi[cur][j][mg];
            float4 oyr4 = sOyr[cur][j][ng], oyi4 = sOyi[cur][j][ng];
            float4 vxr4 = sVxr[cur][j][ng], vxi4 = sVxi[cur][j][ng];
            float vyr[4] = {vyr4.x, vyr4.y, vyr4.z, vyr4.w};
            float vyi[4] = {vyi4.x, vyi4.y, vyi4.z, vyi4.w};
            float oxr[4] = {oxr4.x, oxr4.y, oxr4.z, oxr4.w};
            float oxi[4] = {oxi4.x, oxi4.y, oxi4.z, oxi4.w};
            float oyr[4] = {oyr4.x, oyr4.y, oyr4.z, oyr4.w};
            float oyi[4] = {oyi4.x, oyi4.y, oyi4.z, oyi4.w};
            float vxr[4] = {vxr4.x, vxr4.y, vxr4.z, vxr4.w};
            float vxi[4] = {vxi4.x, vxi4.y, vxi4.z, vxi4.w};
#pragma unroll
            for (int a = 0; a < 4; a++)
#pragma unroll
                for (int q2 = 0; q2 < 4; q2++) {
                    float s = acc[a][q2];
                    s = fmaf(vyr[a], oyr[q2], s);
                    s = fmaf(vyi[a], oyi[q2], s);
                    s = fmaf(oxr[a], vxr[q2], s);
                    s = fmaf(oxi[a], vxi[q2], s);
                    acc[a][q2] = s;
                }
        }
        __syncthreads();
    }

    if (ng < nlim && mg < mlim) {
        float* xb = g_x1 + (size_t)bo * PLANE;
        int n = n0 + ng * 4;
#pragma unroll
        for (int a = 0; a < 4; a++) {
            int m = m0 + mg * 4 + a;
            *(float4*)&xb[m * NX + n] =
                make_float4(acc[a][0], acc[a][1], acc[a][2], acc[a][3]);
        }
    }
}

// ---------------- pointwise MLP + residual (x1 gather via cp.async) ----------------
__global__ void __launch_bounds__(256) pwK(const float* __restrict__ w1, const float* __restrict__ b1,
                    const float* __restrict__ w2, const float* __restrict__ b2,
                    int applyGelu) {
    __shared__ float sX[32][128];
    __shared__ float sT[32][132];
    __shared__ float sW1[32][32], sW2[32][32];
    __shared__ float sB1[32], sB2[32];
    int tid = threadIdx.x;

    int p0 = blockIdx.x * 128;
    // stage x1 gather asynchronously first
    {
        int pp = tid & 127, ch = (tid >> 7) * 16;
        int p = p0 + pp;
        int b = p / PLANE, mn = p % PLANE;
        const float* src = g_x1 + ((size_t)b * CW + ch) * PLANE + mn;
#pragma unroll
        for (int cc = 0; cc < 16; cc++) cpa4(&sX[ch + cc][pp], src + (size_t)cc * PLANE);
    }
    CPA_COMMIT();
    // weights overlap the gather
    for (int idx = tid; idx < 1024; idx += 256) {
        int o = idx >> 5, c = idx & 31;
        sW1[c][o] = w1[o * 32 + c];
        sW2[c][o] = w2[o * 32 + c];
    }
    if (tid < 32) { sB1[tid] = b1[tid]; sB2[tid] = b2[tid]; }
    CPA_WAIT0();
    __syncthreads();

    int og = tid >> 5, pg = tid & 31;
    {
        float t[4][4];
#pragma unroll
        for (int a = 0; a < 4; a++) {
            float bb = sB1[og * 4 + a];
#pragma unroll
            for (int j = 0; j < 4; j++) t[a][j] = bb;
        }
#pragma unroll 4
        for (int c = 0; c < 32; c++) {
            float4 x4 = *(const float4*)&sX[c][pg * 4];
            float xv[4] = {x4.x, x4.y, x4.z, x4.w};
            float4 w4 = *(const float4*)&sW1[c][og * 4];
            float wv[4] = {w4.x, w4.y, w4.z, w4.w};
#pragma unroll
            for (int a = 0; a < 4; a++)
#pragma unroll
                for (int j = 0; j < 4; j++) t[a][j] = fmaf(wv[a], xv[j], t[a][j]);
        }
#pragma unroll
        for (int a = 0; a < 4; a++)
            *(float4*)&sT[og * 4 + a][pg * 4] =
                make_float4(geluf(t[a][0]), geluf(t[a][1]), geluf(t[a][2]), geluf(t[a][3]));
    }
    __syncthreads();
    {
        float t[4][4];
#pragma unroll
        for (int a = 0; a < 4; a++) {
            float bb = sB2[og * 4 + a];
#pragma unroll
            for (int j = 0; j < 4; j++) t[a][j] = bb;
        }
#pragma unroll 4
        for (int c = 0; c < 32; c++) {
            float4 x4 = *(const float4*)&sT[c][pg * 4];
            float xv[4] = {x4.x, x4.y, x4.z, x4.w};
            float4 w4 = *(const float4*)&sW2[c][og * 4];
            float wv[4] = {w4.x, w4.y, w4.z, w4.w};
#pragma unroll
            for (int a = 0; a < 4; a++)
#pragma unroll
                for (int j = 0; j < 4; j++) t[a][j] = fmaf(wv[a], xv[j], t[a][j]);
        }
        int pbase = p0 + pg * 4;
#pragma unroll
        for (int a = 0; a < 4; a++) {
            int o = og * 4 + a;
#pragma unroll
            for (int j = 0; j < 4; j++) {
                int p = pbase + j;
                int b = p / PLANE, mn = p % PLANE;
                size_t off = ((size_t)b * CW + o) * PLANE + mn;
                float s = t[a][j];
                if (applyGelu) s = geluf(s);
                g_h[off] += s;
            }
        }
    }
}

// ---------------- final head (h gather via cp.async) ----------------
__global__ void __launch_bounds__(256) finalK(const float* __restrict__ fc1w, const float* __restrict__ fc1b,
                       const float* __restrict__ fc2w, const float* __restrict__ fc2b,
                       float* __restrict__ out) {
    __shared__ float sX[32][68];
    __shared__ float sW1h[32][64];
    __shared__ float sT[64][68];
    __shared__ float sw2[128], sb1[128];
    __shared__ float sRed[4][64];
    int tid = threadIdx.x;

    int p0 = blockIdx.x * 64;
    // stage h gather asynchronously first
    {
        int pp = tid & 63, ch = (tid >> 6) * 8;
        int p = p0 + pp;
        int b = p / PLANE, mn = p % PLANE;
        const float* src = g_h + ((size_t)b * CW + ch) * PLANE + mn;
#pragma unroll
        for (int cc = 0; cc < 8; cc++) cpa4(&sX[ch + cc][pp], src + (size_t)cc * PLANE);
    }
    CPA_COMMIT();
    if (tid < 128) { sw2[tid] = fc2w[tid]; sb1[tid] = fc1b[tid]; }
    CPA_WAIT0();

    float part = 0.f;
    for (int jh = 0; jh < 128; jh += 64) {
        __syncthreads();
        for (int idx = tid; idx < 512; idx += 256) {
            int c = idx >> 4, j4 = idx & 15;
            *(float4*)&sW1h[c][j4 * 4] = *(const float4*)&fc1w[c * 128 + jh + j4 * 4];
        }
        __syncthreads();

        int jg = tid >> 4, pgr = tid & 15;
        float t[4][4];
#pragma unroll
        for (int a = 0; a < 4; a++) {
            float bb = sb1[jh + jg * 4 + a];
#pragma unroll
            for (int j = 0; j < 4; j++) t[a][j] = bb;
        }
#pragma unroll 4
        for (int c = 0; c < 32; c++) {
            float4 x4 = *(const float4*)&sX[c][pgr * 4];
            float xv[4] = {x4.x, x4.y, x4.z, x4.w};
            float4 w4 = *(const float4*)&sW1h[c][jg * 4];
            float wv[4] = {w4.x, w4.y, w4.z, w4.w};
#pragma unroll
            for (int a = 0; a < 4; a++)
#pragma unroll
                for (int j = 0; j < 4; j++) t[a][j] = fmaf(wv[a], xv[j], t[a][j]);
        }
#pragma unroll
        for (int a = 0; a < 4; a++)
            *(float4*)&sT[jg * 4 + a][pgr * 4] =
                make_float4(geluf(t[a][0]), geluf(t[a][1]), geluf(t[a][2]), geluf(t[a][3]));
        __syncthreads();
        {
            int pq = tid & 63, jq = tid >> 6;
            float s = 0.f;
#pragma unroll
            for (int jj = 0; jj < 16; jj++) {
                int j = jq * 16 + jj;
                s = fmaf(sw2[jh + j], sT[j][pq], s);
            }
            part += s;
        }
    }
    __syncthreads();
    {
        int pq = tid & 63, jq = tid >> 6;
        sRed[jq][pq] = part;
    }
    __syncthreads();
    if (tid < 64) {
        out[p0 + tid] = sRed[0][tid] + sRed[1][tid] + sRed[2][tid] + sRed[3][tid] + fc2b[0];
    }
}

// ---------------- launch ----------------
extern "C" void kernel_launch(void* const* d_in, const int* in_sizes, int n_in,
                              void* d_out, int out_size) {
    (void)in_sizes; (void)n_in; (void)out_size;
    const float* x    = (const float*)d_in[0];
    const float* sx   = (const float*)d_in[1];
    const float* sy   = (const float*)d_in[2];
    const float* fc0w = (const float*)d_in[3];
    const float* fc0b = (const float*)d_in[4];
    const float* fw1  = (const float*)d_in[5];
    const float* fw2  = (const float*)d_in[6];
    const float* w1   = (const float*)d_in[7];
    const float* b1   = (const float*)d_in[8];
    const float* w2   = (const float*)d_in[9];
    const float* b2   = (const float*)d_in[10];
    const float* fc1w = (const float*)d_in[11];
    const float* fc1b = (const float*)d_in[12];
    const float* fc2w = (const float*)d_in[13];
    const float* fc2b = (const float*)d_in[14];
    float* out = (float*)d_out;

    precomputeK<<<64, 256>>>(sx, sy);
    fc0K<<<PIX / 128, 256>>>(x, fc0w, fc0b);

    for (int blk = 0; blk < 4; blk++) {
        const float* fw1p = fw1 + (size_t)blk * CW * CW * KM * 2;
        const float* fw2p = fw2 + (size_t)blk * CW * CW * KM * 2;
        const float* w1p  = w1 + (size_t)blk * CW * CW;
        const float* b1p  = b1 + (size_t)blk * CW;
        const float* w2p  = w2 + (size_t)blk * CW * CW;
        const float* b2p  = b2 + (size_t)blk * CW;

        ftK<<<dim3(5, BSZ * CW), 256>>>();
        mixFK<<<dim3(5, KM, BSZ), 256>>>(fw1p, fw2p);
        invK<<<dim3(6, 3, BSZ * CW), 256>>>();
        pwK<<<PIX / 128, 256>>>(w1p, b1p, w2p, b2p, blk < 3 ? 1 : 0);
    }

    finalK<<<PIX / 64, 256>>>(fc1w, fc1b, fc2w, fc2b, out);
}

// round 11
// speedup vs baseline: 1.1032x; 1.0012x over previous
#include <cuda_runtime.h>
#include <math.h>

#define BSZ 16
#define CW  32
#define MY  180
#define NX  360
#define KM  32
#define PLANE (MY*NX)
#define PIX (BSZ*PLANE)

__device__ __forceinline__ float geluf(float x) {
    return 0.5f * x * (1.0f + erff(x * 0.70710678118654752f));
}

__device__ __forceinline__ void cpa16(void* dst, const void* src, int szbytes) {
    unsigned d = (unsigned)__cvta_generic_to_shared(dst);
    asm volatile("cp.async.cg.shared.global [%0], [%1], 16, %2;"
                 :: "r"(d), "l"(src), "r"(szbytes) : "memory");
}
#define CPA_COMMIT() asm volatile("cp.async.commit_group;" ::: "memory")
#define CPA_WAIT0()  asm volatile("cp.async.wait_group 0;" ::: "memory")
#define CPA_WAIT1()  asm volatile("cp.async.wait_group 1;" ::: "memory")

// ---------------- device scratch ----------------
__device__ __align__(16) float g_h  [BSZ*CW*PLANE];
__device__ __align__(16) float g_x1 [BSZ*CW*PLANE];
__device__ __align__(16) float g_ftyr[BSZ*CW*KM*NX];
__device__ __align__(16) float g_ftyi[BSZ*CW*KM*NX];
__device__ __align__(16) float g_oyr [BSZ*CW*KM*NX];
__device__ __align__(16) float g_oyi [BSZ*CW*KM*NX];
__device__ __align__(16) float g_ftxr[BSZ*CW*KM*MY];
__device__ __align__(16) float g_ftxi[BSZ*CW*KM*MY];
__device__ __align__(16) float g_oxr [BSZ*CW*KM*MY];
__device__ __align__(16) float g_oxi [BSZ*CW*KM*MY];
__device__ __align__(16) float g_Vyr [KM*MY], g_Vyi [KM*MY];   // [k][m]
__device__ __align__(16) float g_Vymr[MY*KM], g_Vymi[MY*KM];   // [m][k]
__device__ __align__(16) float g_Vxr [KM*NX], g_Vxi [KM*NX];   // [k][n]
__device__ __align__(16) float g_Vxnr[NX*KM], g_Vxni[NX*KM];   // [n][k]
__device__ float g_gx[NX], g_gy[MY];

// ---------------- precompute ----------------
__global__ void precomputeK(const float* __restrict__ sx,
                            const float* __restrict__ sy) {
    int t = blockIdx.x * blockDim.x + threadIdx.x;
    int stride = gridDim.x * blockDim.x;
    float x0 = sx[0], xL = sx[NX - 1];
    float y0 = sy[0], yL = sy[MY - 1];
    float invRX = 1.0f / (xL - x0), invRY = 1.0f / (yL - y0);
    float invSqN = rsqrtf((float)NX), invSqM = rsqrtf((float)MY);
    const float TWO_PI = 6.283185307179586f;

    for (int idx = t; idx < KM * NX; idx += stride) {
        int k = idx / NX, n = idx % NX;
        float p = (sx[n] - x0) * invRX;
        float s, c; sincosf(-TWO_PI * (float)k * p, &s, &c);
        float vr = c * invSqN, vi = s * invSqN;
        g_Vxr[idx] = vr; g_Vxi[idx] = vi;
        g_Vxnr[n * KM + k] = vr; g_Vxni[n * KM + k] = vi;
    }
    for (int idx = t; idx < KM * MY; idx += stride) {
        int k = idx / MY, m = idx % MY;
        float p = (sy[m] - y0) * invRY;
        float s, c; sincosf(-TWO_PI * (float)k * p, &s, &c);
        float vr = c * invSqM, vi = s * invSqM;
        g_Vyr[idx] = vr; g_Vyi[idx] = vi;
        g_Vymr[m * KM + k] = vr; g_Vymi[m * KM + k] = vi;
    }
    for (int n = t; n < NX; n += stride) g_gx[n] = (sx[n] - x0) / xL;
    for (int m = t; m < MY; m += stride) g_gy[m] = (sy[m] - y0) / yL;
}

// ---------------- fc0 ----------------
__global__ void fc0K(const float* __restrict__ x,
                     const float* __restrict__ w,
                     const float* __restrict__ bias) {
    __shared__ float sX[18][128];
    __shared__ float sW[18][32];
    __shared__ float sB[32];
    int tid = threadIdx.x;
    for (int idx = tid; idx < 18 * 32; idx += 256) sW[idx >> 5][idx & 31] = w[idx];
    if (tid < 32) sB[tid] = bias[tid];

    int p0 = blockIdx.x * 128;
    {
        int pp = tid & 127, hf = tid >> 7;
        int p = p0 + pp;
        const float4* xp = (const float4*)(x + (size_t)p * 16) + hf * 2;
        float4 a = xp[0], b4 = xp[1];
        int c0 = hf * 8;
        sX[c0 + 0][pp] = a.x;  sX[c0 + 1][pp] = a.y;
        sX[c0 + 2][pp] = a.z;  sX[c0 + 3][pp] = a.w;
        sX[c0 + 4][pp] = b4.x; sX[c0 + 5][pp] = b4.y;
        sX[c0 + 6][pp] = b4.z; sX[c0 + 7][pp] = b4.w;
        if (hf == 0) {
            int mn = p % PLANE;
            sX[16][pp] = g_gx[mn % NX];
            sX[17][pp] = g_gy[mn / NX];
        }
    }
    __syncthreads();

    int og = tid >> 5, pg = tid & 31;
    float t[4][4];
#pragma unroll
    for (int a = 0; a < 4; a++) {
        float bb = sB[og * 4 + a];
#pragma unroll
        for (int j = 0; j < 4; j++) t[a][j] = bb;
    }

#pragma unroll 2
    for (int c = 0; c < 18; c++) {
        float4 x4 = *(const float4*)&sX[c][pg * 4];
        float xv[4] = {x4.x, x4.y, x4.z, x4.w};
        float4 w4 = *(const float4*)&sW[c][og * 4];
        float wv[4] = {w4.x, w4.y, w4.z, w4.w};
#pragma unroll
        for (int a = 0; a < 4; a++)
#pragma unroll
            for (int j = 0; j < 4; j++) t[a][j] = fmaf(wv[a], xv[j], t[a][j]);
    }
#pragma unroll
    for (int a = 0; a < 4; a++) {
        int o = og * 4 + a;
#pragma unroll
        for (int j = 0; j < 4; j++) {
            int p = p0 + pg * 4 + j;
            int b = p / PLANE, mn = p % PLANE;
            g_h[((size_t)b * CW + o) * PLANE + mn] = t[a][j];
        }
    }
}

// ---------------- fused forward transforms (fty 3-stage ring, 1 barrier/chunk) ----------------
__global__ void __launch_bounds__(256) ftK() {
    int bi = blockIdx.y;
    int tid = threadIdx.x;
    const float* hb = g_h + (size_t)bi * PLANE;

    // union smem: fty 3-stage needs 46080B, ftx needs 28224B
    __shared__ __align__(16) char sBuf[46080];

    if (blockIdx.x < 3) {
        // ---- fty: FTY[k][n] = sum_m Vy[k][m] * H[m][n], 9 chunks of 20 m, 3-deep ring ----
        float4* sH  = (float4*)sBuf;            // [3][20][32]  (3*640 float4)
        float4* sVr = (float4*)(sBuf + 30720);  // [3][20][8]
        float4* sVi = (float4*)(sBuf + 38400);  // [3][20][8]

        int n0 = blockIdx.x * 128;
        int kg = tid >> 5, ng = tid & 31;

        float cr[4][4], ci[4][4];
#pragma unroll
        for (int a = 0; a < 4; a++)
#pragma unroll
            for (int j = 0; j < 4; j++) { cr[a][j] = 0.f; ci[a][j] = 0.f; }

        // prologue: stage chunks 0 and 1 (one commit group each)
#pragma unroll
        for (int pc = 0; pc < 2; pc++) {
            int m0 = pc * 20;
            int buf = pc;
            for (int idx = tid; idx < 640; idx += 256) {
                int mm = idx >> 5, n4 = idx & 31;
                int gn = n0 + n4 * 4;
                cpa16(&sH[buf * 640 + idx], &hb[(m0 + mm) * NX + gn], (gn < NX) ? 16 : 0);
            }
            for (int idx = tid; idx < 160; idx += 256) {
                int mm = idx >> 3, k4 = idx & 7;
                cpa16(&sVr[buf * 160 + idx], &g_Vymr[(m0 + mm) * KM + k4 * 4], 16);
                cpa16(&sVi[buf * 160 + idx], &g_Vymi[(m0 + mm) * KM + k4 * 4], 16);
            }
            CPA_COMMIT();
        }

        for (int c = 0; c < 9; c++) {
            if (c < 8) { CPA_WAIT1(); } else { CPA_WAIT0(); }
            __syncthreads();   // chunk c ready; all warps finished chunk c-1

            // prefetch chunk c+2 into buffer (c+2)%3 (overwrites c-1's buffer: safe)
            if (c + 2 <= 8) {
                int m0 = (c + 2) * 20;
                int buf = (c + 2) % 3;
                for (int idx = tid; idx < 640; idx += 256) {
                    int mm = idx >> 5, n4 = idx & 31;
                    int gn = n0 + n4 * 4;
                    cpa16(&sH[buf * 640 + idx], &hb[(m0 + mm) * NX + gn], (gn < NX) ? 16 : 0);
                }
                for (int idx = tid; idx < 160; idx += 256) {
                    int mm = idx >> 3, k4 = idx & 7;
                    cpa16(&sVr[buf * 160 + idx], &g_Vymr[(m0 + mm) * KM + k4 * 4], 16);
                    cpa16(&sVi[buf * 160 + idx], &g_Vymi[(m0 + mm) * KM + k4 * 4], 16);
                }
                CPA_COMMIT();
            }

            int cur = c % 3;
#pragma unroll 5
            for (int mm = 0; mm < 20; mm++) {
                float4 h4 = sH[cur * 640 + mm * 32 + ng];
                float hv[4] = {h4.x, h4.y, h4.z, h4.w};
                float4 vr4 = sVr[cur * 160 + mm * 8 + kg];
                float4 vi4 = sVi[cur * 160 + mm * 8 + kg];
                float vr[4] = {vr4.x, vr4.y, vr4.z, vr4.w};
                float vi[4] = {vi4.x, vi4.y, vi4.z, vi4.w};
#pragma unroll
                for (int a = 0; a < 4; a++)
#pragma unroll
                    for (int j = 0; j < 4; j++) {
                        cr[a][j] = fmaf(vr[a], hv[j], cr[a][j]);
                        ci[a][j] = fmaf(vi[a], hv[j], ci[a][j]);
                    }
            }
        }
        int n = n0 + ng * 4;
        if (n < NX) {
#pragma unroll
            for (int a = 0; a < 4; a++) {
                int k = kg * 4 + a;
                size_t off = ((size_t)bi * KM + k) * NX + n;
                *(float4*)&g_ftyr[off] = make_float4(cr[a][0], cr[a][1], cr[a][2], cr[a][3]);
                *(float4*)&g_ftyi[off] = make_float4(ci[a][0], ci[a][1], ci[a][2], ci[a][3]);
            }
        }
    } else {
        // ---- ftx: FTX[k][m] = sum_n Vx[k][n] * H[m][n] ----
        float4* sVr2 = (float4*)sBuf;            // [36][8]
        float4* sVi2 = (float4*)(sBuf + 4608);   // [36][8]
        float*  sHT  = (float*)(sBuf + 9216);    // [36][132]

        int m0 = (blockIdx.x - 3) * 128;
        int kg = tid >> 5, mg = tid & 31;

        float cr[4][4], ci[4][4];
#pragma unroll
        for (int a = 0; a < 4; a++)
#pragma unroll
            for (int j = 0; j < 4; j++) { cr[a][j] = 0.f; ci[a][j] = 0.f; }

        for (int n0 = 0; n0 < NX; n0 += 36) {
            for (int idx = tid; idx < 1152; idx += 256) {
                int m = idx / 9, q = idx % 9;
                int gm = m0 + m;
                float4 v = (gm < MY) ? *(const float4*)&hb[gm * NX + n0 + q * 4]
                                     : make_float4(0.f, 0.f, 0.f, 0.f);
                int nn = q * 4;
                sHT[nn * 132 + m] = v.x; sHT[(nn + 1) * 132 + m] = v.y;
                sHT[(nn + 2) * 132 + m] = v.z; sHT[(nn + 3) * 132 + m] = v.w;
            }
            for (int idx = tid; idx < 288; idx += 256) {
                int nn = idx >> 3, k4 = idx & 7;
                sVr2[nn * 8 + k4] = *(const float4*)&g_Vxnr[(n0 + nn) * KM + k4 * 4];
                sVi2[nn * 8 + k4] = *(const float4*)&g_Vxni[(n0 + nn) * KM + k4 * 4];
            }
            __syncthreads();
#pragma unroll 6
            for (int nn = 0; nn < 36; nn++) {
                float4 h4 = *(const float4*)&sHT[nn * 132 + mg * 4];
                float hv[4] = {h4.x, h4.y, h4.z, h4.w};
                float4 vr4 = sVr2[nn * 8 + kg];
                float4 vi4 = sVi2[nn * 8 + kg];
                float vr[4] = {vr4.x, vr4.y, vr4.z, vr4.w};
                float vi[4] = {vi4.x, vi4.y, vi4.z, vi4.w};
#pragma unroll
                for (int a = 0; a < 4; a++)
#pragma unroll
                    for (int j = 0; j < 4; j++) {
                        cr[a][j] = fmaf(vr[a], hv[j], cr[a][j]);
                        ci[a][j] = fmaf(vi[a], hv[j], ci[a][j]);
                    }
            }
            __syncthreads();
        }
        int m = m0 + mg * 4;
        if (m < MY) {
#pragma unroll
            for (int a = 0; a < 4; a++) {
                int k = kg * 4 + a;
                size_t off = ((size_t)bi * KM + k) * MY + m;
                *(float4*)&g_ftxr[off] = make_float4(cr[a][0], cr[a][1], cr[a][2], cr[a][3]);
                *(float4*)&g_ftxi[off] = make_float4(ci[a][0], ci[a][1], ci[a][2], ci[a][3]);
            }
        }
    }
}

// ---------------- fused mode mix (two-phase cp.async overlap) ----------------
__global__ void __launch_bounds__(256) mixFK(const float* __restrict__ fw1,
                                             const float* __restrict__ fw2) {
    int isY = (blockIdx.x < 3);
    const float* fw = isY ? fw1 : fw2;
    const float* finr = isY ? g_ftyr : g_ftxr;
    const float* fini = isY ? g_ftyi : g_ftxi;
    float* foutr = isY ? g_oyr : g_oxr;
    float* fouti = isY ? g_oyi : g_oxi;
    int L = isY ? NX : MY;
    int l0 = (isY ? blockIdx.x : (blockIdx.x - 3)) * 128;

    int b = blockIdx.z, k = blockIdx.y;
    int tid = threadIdx.x;
    int og = tid >> 5, lg = tid & 31;

    __shared__ float  sWr[32][32], sWi[32][32];
    __shared__ float4 sFr[32][32], sFi[32][32];

    for (int idx = tid; idx < 512; idx += 256) {
        int i = idx >> 5, l4 = idx & 31;
        int gl = l0 + l4 * 4;
        size_t off = ((size_t)(b * CW + i) * KM + k) * L + gl;
        int sz = (gl < L) ? 16 : 0;
        cpa16(&sFr[i][l4], &finr[off], sz);
        cpa16(&sFi[i][l4], &fini[off], sz);
    }
    CPA_COMMIT();
    for (int idx = 512 + tid; idx < 1024; idx += 256) {
        int i = idx >> 5, l4 = idx & 31;
        int gl = l0 + l4 * 4;
        size_t off = ((size_t)(b * CW + i) * KM + k) * L + gl;
        int sz = (gl < L) ? 16 : 0;
        cpa16(&sFr[i][l4], &finr[off], sz);
        cpa16(&sFi[i][l4], &fini[off], sz);
    }
    CPA_COMMIT();
    for (int idx = tid; idx < 1024; idx += 256) {
        int i = idx >> 5, o = idx & 31;
        const float* p = fw + ((size_t)(i * 32 + o) * KM + k) * 2;
        sWr[i][o] = p[0]; sWi[i][o] = p[1];
    }

    float cr[4][4], ci[4][4];
#pragma unroll
    for (int a = 0; a < 4; a++)
#pragma unroll
        for (int j = 0; j < 4; j++) { cr[a][j] = 0.f; ci[a][j] = 0.f; }

    CPA_WAIT1();
    __syncthreads();

#pragma unroll 4
    for (int i = 0; i < 16; i++) {
        float4 fr4 = sFr[i][lg], fi4 = sFi[i][lg];
        float fr[4] = {fr4.x, fr4.y, fr4.z, fr4.w};
        float fi[4] = {fi4.x, fi4.y, fi4.z, fi4.w};
        float4 wr4 = *(const float4*)&sWr[i][og * 4];
        float4 wi4 = *(const float4*)&sWi[i][og * 4];
        float wr[4] = {wr4.x, wr4.y, wr4.z, wr4.w};
        float wi[4] = {wi4.x, wi4.y, wi4.z, wi4.w};
#pragma unroll
        for (int a = 0; a < 4; a++) {
            float wrv = wr[a], wiv = wi[a];
#pragma unroll
            for (int j = 0; j < 4; j++) {
                cr[a][j] = fmaf(wrv, fr[j], cr[a][j]);
                cr[a][j] = fmaf(-wiv, fi[j], cr[a][j]);
                ci[a][j] = fmaf(wrv, fi[j], ci[a][j]);
                ci[a][j] = fmaf(wiv, fr[j], ci[a][j]);
            }
        }
    }

    CPA_WAIT0();
    __syncthreads();

#pragma unroll 4
    for (int i = 16; i < 32; i++) {
        float4 fr4 = sFr[i][lg], fi4 = sFi[i][lg];
        float fr[4] = {fr4.x, fr4.y, fr4.z, fr4.w};
        float fi[4] = {fi4.x, fi4.y, fi4.z, fi4.w};
        float4 wr4 = *(const float4*)&sWr[i][og * 4];
        float4 wi4 = *(const float4*)&sWi[i][og * 4];
        float wr[4] = {wr4.x, wr4.y, wr4.z, wr4.w};
        float wi[4] = {wi4.x, wi4.y, wi4.z, wi4.w};
#pragma unroll
        for (int a = 0; a < 4; a++) {
            float wrv = wr[a], wiv = wi[a];
#pragma unroll
            for (int j = 0; j < 4; j++) {
                cr[a][j] = fmaf(wrv, fr[j], cr[a][j]);
                cr[a][j] = fmaf(-wiv, fi[j], cr[a][j]);
                ci[a][j] = fmaf(wrv, fi[j], ci[a][j]);
                ci[a][j] = fmaf(wiv, fr[j], ci[a][j]);
            }
        }
    }

    int gl = l0 + lg * 4;
    if (gl < L) {
#pragma unroll
        for (int a = 0; a < 4; a++) {
            int o = og * 4 + a;
            size_t off = ((size_t)(b * CW + o) * KM + k) * L + gl;
            *(float4*)&foutr[off] = make_float4(cr[a][0], cr[a][1], cr[a][2], cr[a][3]);
            *(float4*)&fouti[off] = make_float4(ci[a][0], ci[a][1], ci[a][2], ci[a][3]);
        }
    }
}

// ---------------- fused inverse: x1 = invY + invX, 4 k-chunks, 3-stage ring ----------------
__global__ void __launch_bounds__(256) invK() {
    int bo = blockIdx.z;
    int m0 = blockIdx.y * 64;
    int n0 = blockIdx.x * 64;
    int tid = threadIdx.x;
    int mg = tid >> 4, ng = tid & 15;
    int mlim = (m0 == 128) ? 13 : 16;
    int nlim = (n0 == 320) ? 10 : 16;

    // 8 arrays x [3 buf][8 k][16 q] float4 = 48KB
    __shared__ float4 sVyr[3][8][16], sVyi[3][8][16], sOxr[3][8][16], sOxi[3][8][16];
    __shared__ float4 sOyr[3][8][16], sOyi[3][8][16], sVxr[3][8][16], sVxi[3][8][16];

    float acc[4][4];
#pragma unroll
    for (int a = 0; a < 4; a++)
#pragma unroll
        for (int j = 0; j < 4; j++) acc[a][j] = 0.f;

    // prologue: stage chunks 0 and 1
#pragma unroll
    for (int pc = 0; pc < 2; pc++) {
        if (tid < 128) {
            int kk = tid >> 4, q = tid & 15;
            int kabs = pc * 8 + kk;
            int msz = (q < mlim) ? 16 : 0;
            int nsz = (q < nlim) ? 16 : 0;
            size_t obY = ((size_t)bo * KM + kabs) * NX + n0 + q * 4;
            size_t obX = ((size_t)bo * KM + kabs) * MY + m0 + q * 4;
            cpa16(&sVyr[pc][kk][q], &g_Vyr[kabs * MY + m0 + q * 4], msz);
            cpa16(&sVyi[pc][kk][q], &g_Vyi[kabs * MY + m0 + q * 4], msz);
            cpa16(&sOxr[pc][kk][q], &g_oxr[obX], msz);
            cpa16(&sOxi[pc][kk][q], &g_oxi[obX], msz);
            cpa16(&sOyr[pc][kk][q], &g_oyr[obY], nsz);
            cpa16(&sOyi[pc][kk][q], &g_oyi[obY], nsz);
            cpa16(&sVxr[pc][kk][q], &g_Vxr[kabs * NX + n0 + q * 4], nsz);
            cpa16(&sVxi[pc][kk][q], &g_Vxi[kabs * NX + n0 + q * 4], nsz);
        }
        CPA_COMMIT();
    }

    for (int c = 0; c < 4; c++) {
        if (c < 3) { CPA_WAIT1(); } else { CPA_WAIT0(); }
        __syncthreads();   // chunk c ready; all warps done with chunk c-1

        if (c + 2 <= 3) {
            int buf = (c + 2) % 3;
            if (tid < 128) {
                int kk = tid >> 4, q = tid & 15;
                int kabs = (c + 2) * 8 + kk;
                int msz = (q < mlim) ? 16 : 0;
                int nsz = (q < nlim) ? 16 : 0;
                size_t obY = ((size_t)bo * KM + kabs) * NX + n0 + q * 4;
                size_t obX = ((size_t)bo * KM + kabs) * MY + m0 + q * 4;
                cpa16(&sVyr[buf][kk][q], &g_Vyr[kabs * MY + m0 + q * 4], msz);
                cpa16(&sVyi[buf][kk][q], &g_Vyi[kabs * MY + m0 + q * 4], msz);
                cpa16(&sOxr[buf][kk][q], &g_oxr[obX], msz);
                cpa16(&sOxi[buf][kk][q], &g_oxi[obX], msz);
                cpa16(&sOyr[buf][kk][q], &g_oyr[obY], nsz);
                cpa16(&sOyi[buf][kk][q], &g_oyi[obY], nsz);
                cpa16(&sVxr[buf][kk][q], &g_Vxr[kabs * NX + n0 + q * 4], nsz);
                cpa16(&sVxi[buf][kk][q], &g_Vxi[kabs * NX + n0 + q * 4], nsz);
            }
            CPA_COMMIT();
        }

        int cur = c % 3;
#pragma unroll
        for (int j = 0; j < 8; j++) {
            float4 vyr4 = sVyr[cur][j][mg], vyi4 = sVyi[cur][j][mg];
            float4 oxr4 = sOxr[cur][j][mg], oxi4 = sOxi[cur][j][mg];
            float4 oyr4 = sOyr[cur][j][ng], oyi4 = sOyi[cur][j][ng];
            float4 vxr4 = sVxr[cur][j][ng], vxi4 = sVxi[cur][j][ng];
            float vyr[4] = {vyr4.x, vyr4.y, vyr4.z, vyr4.w};
            float vyi[4] = {vyi4.x, vyi4.y, vyi4.z, vyi4.w};
            float oxr[4] = {oxr4.x, oxr4.y, oxr4.z, oxr4.w};
            float oxi[4] = {oxi4.x, oxi4.y, oxi4.z, oxi4.w};
            float oyr[4] = {oyr4.x, oyr4.y, oyr4.z, oyr4.w};
            float oyi[4] = {oyi4.x, oyi4.y, oyi4.z, oyi4.w};
            float vxr[4] = {vxr4.x, vxr4.y, vxr4.z, vxr4.w};
            float vxi[4] = {vxi4.x, vxi4.y, vxi4.z, vxi4.w};
#pragma unroll
            for (int a = 0; a < 4; a++)
#pragma unroll
                for (int q2 = 0; q2 < 4; q2++) {
                    float s = acc[a][q2];
                    s = fmaf(vyr[a], oyr[q2], s);
                    s = fmaf(vyi[a], oyi[q2], s);
                    s = fmaf(oxr[a], vxr[q2], s);
                    s = fmaf(oxi[a], vxi[q2], s);
                    acc[a][q2] = s;
                }
        }
    }

    if (ng < nlim && mg < mlim) {
        float* xb = g_x1 + (size_t)bo * PLANE;
        int n = n0 + ng * 4;
#pragma unroll
        for (int a = 0; a < 4; a++) {
            int m = m0 + mg * 4 + a;
            *(float4*)&xb[m * NX + n] =
                make_float4(acc[a][0], acc[a][1], acc[a][2], acc[a][3]);
        }
    }
}

// ---------------- pointwise MLP + residual ----------------
__global__ void __launch_bounds__(256) pwK(const float* __restrict__ w1, const float* __restrict__ b1,
                    const float* __restrict__ w2, const float* __restrict__ b2,
                    int applyGelu) {
    __shared__ float sX[32][128];
    __shared__ float sT[32][132];
    __shared__ float sW1[32][32], sW2[32][32];
    __shared__ float sB1[32], sB2[32];
    int tid = threadIdx.x;
    for (int idx = tid; idx < 1024; idx += 256) {
        int o = idx >> 5, c = idx & 31;
        sW1[c][o] = w1[o * 32 + c];
        sW2[c][o] = w2[o * 32 + c];
    }
    if (tid < 32) { sB1[tid] = b1[tid]; sB2[tid] = b2[tid]; }

    int p0 = blockIdx.x * 128;
    {
        int pp = tid & 127, ch = (tid >> 7) * 16;
        int p = p0 + pp;
        int b = p / PLANE, mn = p % PLANE;
        const float* src = g_x1 + ((size_t)b * CW + ch) * PLANE + mn;
#pragma unroll
        for (int cc = 0; cc < 16; cc++) sX[ch + cc][pp] = src[(size_t)cc * PLANE];
    }
    __syncthreads();

    int og = tid >> 5, pg = tid & 31;
    {
        float t[4][4];
#pragma unroll
        for (int a = 0; a < 4; a++) {
            float bb = sB1[og * 4 + a];
#pragma unroll
            for (int j = 0; j < 4; j++) t[a][j] = bb;
        }
#pragma unroll 4
        for (int c = 0; c < 32; c++) {
            float4 x4 = *(const float4*)&sX[c][pg * 4];
            float xv[4] = {x4.x, x4.y, x4.z, x4.w};
            float4 w4 = *(const float4*)&sW1[c][og * 4];
            float wv[4] = {w4.x, w4.y, w4.z, w4.w};
#pragma unroll
            for (int a = 0; a < 4; a++)
#pragma unroll
                for (int j = 0; j < 4; j++) t[a][j] = fmaf(wv[a], xv[j], t[a][j]);
        }
#pragma unroll
        for (int a = 0; a < 4; a++)
            *(float4*)&sT[og * 4 + a][pg * 4] =
                make_float4(geluf(t[a][0]), geluf(t[a][1]), geluf(t[a][2]), geluf(t[a][3]));
    }
    __syncthreads();
    {
        float t[4][4];
#pragma unroll
        for (int a = 0; a < 4; a++) {
            float bb = sB2[og * 4 + a];
#pragma unroll
            for (int j = 0; j < 4; j++) t[a][j] = bb;
        }
#pragma unroll 4
        for (int c = 0; c < 32; c++) {
            float4 x4 = *(const float4*)&sT[c][pg * 4];
            float xv[4] = {x4.x, x4.y, x4.z, x4.w};
            float4 w4 = *(const float4*)&sW2[c][og * 4];
            float wv[4] = {w4.x, w4.y, w4.z, w4.w};
#pragma unroll
            for (int a = 0; a < 4; a++)
#pragma unroll
                for (int j = 0; j < 4; j++) t[a][j] = fmaf(wv[a], xv[j], t[a][j]);
        }
        int pbase = p0 + pg * 4;
#pragma unroll
        for (int a = 0; a < 4; a++) {
            int o = og * 4 + a;
#pragma unroll
            for (int j = 0; j < 4; j++) {
                int p = pbase + j;
                int b = p / PLANE, mn = p % PLANE;
                size_t off = ((size_t)b * CW + o) * PLANE + mn;
                float s = t[a][j];
                if (applyGelu) s = geluf(s);
                g_h[off] += s;
            }
        }
    }
}

// ---------------- final head ----------------
__global__ void __launch_bounds__(256) finalK(const float* __restrict__ fc1w, const float* __restrict__ fc1b,
                       const float* __restrict__ fc2w, const float* __restrict__ fc2b,
                       float* __restrict__ out) {
    __shared__ float sX[32][68];
    __shared__ float sW1h[32][64];
    __shared__ float sT[64][68];
    __shared__ float sw2[128], sb1[128];
    __shared__ float sRed[4][64];
    int tid = threadIdx.x;
    if (tid < 128) { sw2[tid] = fc2w[tid]; sb1[tid] = fc1b[tid]; }

    int p0 = blockIdx.x * 64;
    {
        int pp = tid & 63, ch = (tid >> 6) * 8;
        int p = p0 + pp;
        int b = p / PLANE, mn = p % PLANE;
        const float* src = g_h + ((size_t)b * CW + ch) * PLANE + mn;
#pragma unroll
        for (int cc = 0; cc < 8; cc++) sX[ch + cc][pp] = src[(size_t)cc * PLANE];
    }

    float part = 0.f;
    for (int jh = 0; jh < 128; jh += 64) {
        __syncthreads();
        for (int idx = tid; idx < 512; idx += 256) {
            int c = idx >> 4, j4 = idx & 15;
            *(float4*)&sW1h[c][j4 * 4] = *(const float4*)&fc1w[c * 128 + jh + j4 * 4];
        }
        __syncthreads();

        int jg = tid >> 4, pgr = tid & 15;
        float t[4][4];
#pragma unroll
        for (int a = 0; a < 4; a++) {
            float bb = sb1[jh + jg * 4 + a];
#pragma unroll
            for (int j = 0; j < 4; j++) t[a][j] = bb;
        }
#pragma unroll 4
        for (int c = 0; c < 32; c++) {
            float4 x4 = *(const float4*)&sX[c][pgr * 4];
            float xv[4] = {x4.x, x4.y, x4.z, x4.w};
            float4 w4 = *(const float4*)&sW1h[c][jg * 4];
            float wv[4] = {w4.x, w4.y, w4.z, w4.w};
#pragma unroll
            for (int a = 0; a < 4; a++)
#pragma unroll
                for (int j = 0; j < 4; j++) t[a][j] = fmaf(wv[a], xv[j], t[a][j]);
        }
#pragma unroll
        for (int a = 0; a < 4; a++)
            *(float4*)&sT[jg * 4 + a][pgr * 4] =
                make_float4(geluf(t[a][0]), geluf(t[a][1]), geluf(t[a][2]), geluf(t[a][3]));
        __syncthreads();
        {
            int pq = tid & 63, jq = tid >> 6;
            float s = 0.f;
#pragma unroll
            for (int jj = 0; jj < 16; jj++) {
                int j = jq * 16 + jj;
                s = fmaf(sw2[jh + j], sT[j][pq], s);
            }
            part += s;
        }
    }
    __syncthreads();
    {
        int pq = tid & 63, jq = tid >> 6;
        sRed[jq][pq] = part;
    }
    __syncthreads();
    if (tid < 64) {
        out[p0 + tid] = sRed[0][tid] + sRed[1][tid] + sRed[2][tid] + sRed[3][tid] + fc2b[0];
    }
}

// ---------------- launch ----------------
extern "C" void kernel_launch(void* const* d_in, const int* in_sizes, int n_in,
                              void* d_out, int out_size) {
    (void)in_sizes; (void)n_in; (void)out_size;
    const float* x    = (const float*)d_in[0];
    const float* sx   = (const float*)d_in[1];
    const float* sy   = (const float*)d_in[2];
    const float* fc0w = (const float*)d_in[3];
    const float* fc0b = (const float*)d_in[4];
    const float* fw1  = (const float*)d_in[5];
    const float* fw2  = (const float*)d_in[6];
    const float* w1   = (const float*)d_in[7];
    const float* b1   = (const float*)d_in[8];
    const float* w2   = (const float*)d_in[9];
    const float* b2   = (const float*)d_in[10];
    const float* fc1w = (const float*)d_in[11];
    const float* fc1b = (const float*)d_in[12];
    const float* fc2w = (const float*)d_in[13];
    const float* fc2b = (const float*)d_in[14];
    float* out = (float*)d_out;

    precomputeK<<<64, 256>>>(sx, sy);
    fc0K<<<PIX / 128, 256>>>(x, fc0w, fc0b);

    for (int blk = 0; blk < 4; blk++) {
        const float* fw1p = fw1 + (size_t)blk * CW * CW * KM * 2;
        const float* fw2p = fw2 + (size_t)blk * CW * CW * KM * 2;
        const float* w1p  = w1 + (size_t)blk * CW * CW;
        const float* b1p  = b1 + (size_t)blk * CW;
        const float* w2p  = w2 + (size_t)blk * CW * CW;
        const float* b2p  = b2 + (size_t)blk * CW;

        ftK<<<dim3(5, BSZ * CW), 256>>>();
        mixFK<<<dim3(5, KM, BSZ), 256>>>(fw1p, fw2p);
        invK<<<dim3(6, 3, BSZ * CW), 256>>>();
        pwK<<<PIX / 128, 256>>>(w1p, b1p, w2p, b2p, blk < 3 ? 1 : 0);
    }

    finalK<<<PIX / 64, 256>>>(fc1w, fc1b, fc2w, fc2b, out);
}

// round 12
// speedup vs baseline: 1.1097x; 1.0059x over previous
#include <cuda_runtime.h>
#include <cuda_bf16.h>
#include <math.h>

#define BSZ 16
#define CW  32
#define MY  180
#define NX  360
#define KM  32
#define PLANE (MY*NX)
#define PIX (BSZ*PLANE)

__device__ __forceinline__ float geluf(float x) {
    return 0.5f * x * (1.0f + erff(x * 0.70710678118654752f));
}

__device__ __forceinline__ void cpa16(void* dst, const void* src, int szbytes) {
    unsigned d = (unsigned)__cvta_generic_to_shared(dst);
    asm volatile("cp.async.cg.shared.global [%0], [%1], 16, %2;"
                 :: "r"(d), "l"(src), "r"(szbytes) : "memory");
}
#define CPA_COMMIT() asm volatile("cp.async.commit_group;" ::: "memory")
#define CPA_WAIT0()  asm volatile("cp.async.wait_group 0;" ::: "memory")
#define CPA_WAIT1()  asm volatile("cp.async.wait_group 1;" ::: "memory")

// m16n8k16 bf16 MMA, fp32 accum
__device__ __forceinline__ void mma16816(float* d, const unsigned* a, const unsigned* b) {
    asm volatile(
        "mma.sync.aligned.m16n8k16.row.col.f32.bf16.bf16.f32 "
        "{%0,%1,%2,%3},{%4,%5,%6,%7},{%8,%9},{%0,%1,%2,%3};"
        : "+f"(d[0]), "+f"(d[1]), "+f"(d[2]), "+f"(d[3])
        : "r"(a[0]), "r"(a[1]), "r"(a[2]), "r"(a[3]), "r"(b[0]), "r"(b[1]));
}

__device__ __forceinline__ void bsplit(float v, __nv_bfloat16& h, __nv_bfloat16& l) {
    h = __float2bfloat16(v);
    l = __float2bfloat16(v - __bfloat162float(h));
}

// ---------------- device scratch ----------------
__device__ __align__(16) float g_h  [BSZ*CW*PLANE];
__device__ __align__(16) float g_x1 [BSZ*CW*PLANE];
__device__ __align__(16) float g_ftyr[BSZ*CW*KM*NX];
__device__ __align__(16) float g_ftyi[BSZ*CW*KM*NX];
__device__ __align__(16) float g_oyr [BSZ*CW*KM*NX];
__device__ __align__(16) float g_oyi [BSZ*CW*KM*NX];
__device__ __align__(16) float g_ftxr[BSZ*CW*KM*MY];
__device__ __align__(16) float g_ftxi[BSZ*CW*KM*MY];
__device__ __align__(16) float g_oxr [BSZ*CW*KM*MY];
__device__ __align__(16) float g_oxi [BSZ*CW*KM*MY];
__device__ __align__(16) float g_Vyr [KM*MY], g_Vyi [KM*MY];   // [k][m]
__device__ __align__(16) float g_Vxr [KM*NX], g_Vxi [KM*NX];   // [k][n]
// bf16-split stacked V matrices: rows 0..31 = real, 32..63 = imag; K padded
#define KPY 192
#define KPX 384
__device__ __align__(16) __nv_bfloat16 g_Vych[64*KPY], g_Vycl[64*KPY];
__device__ __align__(16) __nv_bfloat16 g_Vxch[64*KPX], g_Vxcl[64*KPX];
__device__ float g_gx[NX], g_gy[MY];

// ---------------- precompute ----------------
__global__ void precomputeK(const float* __restrict__ sx,
                            const float* __restrict__ sy) {
    int t = blockIdx.x * blockDim.x + threadIdx.x;
    int stride = gridDim.x * blockDim.x;
    float x0 = sx[0], xL = sx[NX - 1];
    float y0 = sy[0], yL = sy[MY - 1];
    float invRX = 1.0f / (xL - x0), invRY = 1.0f / (yL - y0);
    float invSqN = rsqrtf((float)NX), invSqM = rsqrtf((float)MY);
    const float TWO_PI = 6.283185307179586f;
    __nv_bfloat16 z16 = __float2bfloat16(0.f);

    // zero padded tails (disjoint from fill regions)
    for (int idx = t; idx < 64 * (KPY - MY); idx += stride) {
        int r = idx / (KPY - MY), m = MY + idx % (KPY - MY);
        g_Vych[r * KPY + m] = z16; g_Vycl[r * KPY + m] = z16;
    }
    for (int idx = t; idx < 64 * (KPX - NX); idx += stride) {
        int r = idx / (KPX - NX), n = NX + idx % (KPX - NX);
        g_Vxch[r * KPX + n] = z16; g_Vxcl[r * KPX + n] = z16;
    }

    for (int idx = t; idx < KM * NX; idx += stride) {
        int k = idx / NX, n = idx % NX;
        float p = (sx[n] - x0) * invRX;
        float s, c; sincosf(-TWO_PI * (float)k * p, &s, &c);
        float vr = c * invSqN, vi = s * invSqN;
        g_Vxr[idx] = vr; g_Vxi[idx] = vi;
        __nv_bfloat16 h16, l16;
        bsplit(vr, h16, l16);
        g_Vxch[k * KPX + n] = h16; g_Vxcl[k * KPX + n] = l16;
        bsplit(vi, h16, l16);
        g_Vxch[(k + 32) * KPX + n] = h16; g_Vxcl[(k + 32) * KPX + n] = l16;
    }
    for (int idx = t; idx < KM * MY; idx += stride) {
        int k = idx / MY, m = idx % MY;
        float p = (sy[m] - y0) * invRY;
        float s, c; sincosf(-TWO_PI * (float)k * p, &s, &c);
        float vr = c * invSqM, vi = s * invSqM;
        g_Vyr[idx] = vr; g_Vyi[idx] = vi;
        __nv_bfloat16 h16, l16;
        bsplit(vr, h16, l16);
        g_Vych[k * KPY + m] = h16; g_Vycl[k * KPY + m] = l16;
        bsplit(vi, h16, l16);
        g_Vych[(k + 32) * KPY + m] = h16; g_Vycl[(k + 32) * KPY + m] = l16;
    }
    for (int n = t; n < NX; n += stride) g_gx[n] = (sx[n] - x0) / xL;
    for (int m = t; m < MY; m += stride) g_gy[m] = (sy[m] - y0) / yL;
}

// ---------------- fc0 ----------------
__global__ void fc0K(const float* __restrict__ x,
                     const float* __restrict__ w,
                     const float* __restrict__ bias) {
    __shared__ float sX[18][128];
    __shared__ float sW[18][32];
    __shared__ float sB[32];
    int tid = threadIdx.x;
    for (int idx = tid; idx < 18 * 32; idx += 256) sW[idx >> 5][idx & 31] = w[idx];
    if (tid < 32) sB[tid] = bias[tid];

    int p0 = blockIdx.x * 128;
    {
        int pp = tid & 127, hf = tid >> 7;
        int p = p0 + pp;
        const float4* xp = (const float4*)(x + (size_t)p * 16) + hf * 2;
        float4 a = xp[0], b4 = xp[1];
        int c0 = hf * 8;
        sX[c0 + 0][pp] = a.x;  sX[c0 + 1][pp] = a.y;
        sX[c0 + 2][pp] = a.z;  sX[c0 + 3][pp] = a.w;
        sX[c0 + 4][pp] = b4.x; sX[c0 + 5][pp] = b4.y;
        sX[c0 + 6][pp] = b4.z; sX[c0 + 7][pp] = b4.w;
        if (hf == 0) {
            int mn = p % PLANE;
            sX[16][pp] = g_gx[mn % NX];
            sX[17][pp] = g_gy[mn / NX];
        }
    }
    __syncthreads();

    int og = tid >> 5, pg = tid & 31;
    float t[4][4];
#pragma unroll
    for (int a = 0; a < 4; a++) {
        float bb = sB[og * 4 + a];
#pragma unroll
        for (int j = 0; j < 4; j++) t[a][j] = bb;
    }

#pragma unroll 2
    for (int c = 0; c < 18; c++) {
        float4 x4 = *(const float4*)&sX[c][pg * 4];
        float xv[4] = {x4.x, x4.y, x4.z, x4.w};
        float4 w4 = *(const float4*)&sW[c][og * 4];
        float wv[4] = {w4.x, w4.y, w4.z, w4.w};
#pragma unroll
        for (int a = 0; a < 4; a++)
#pragma unroll
            for (int j = 0; j < 4; j++) t[a][j] = fmaf(wv[a], xv[j], t[a][j]);
    }
#pragma unroll
    for (int a = 0; a < 4; a++) {
        int o = og * 4 + a;
#pragma unroll
        for (int j = 0; j < 4; j++) {
            int p = p0 + pg * 4 + j;
            int b = p / PLANE, mn = p % PLANE;
            g_h[((size_t)b * CW + o) * PLANE + mn] = t[a][j];
        }
    }
}

// ---------------- tensor-core forward transforms ----------------
// C[64 stacked modes][128 cols] = Vcat[64 x Kpad] * X[Kpad x 128], bf16x2 split (3 MMAs).
// blockIdx.x < 3 : fty (cols = n, K = m);  else : ftx (cols = m, K = n).
__global__ void __launch_bounds__(256) ftK() {
    int bi = blockIdx.y;
    int tid = threadIdx.x;
    int lane = tid & 31, wid = tid >> 5;
    int wrow = (wid & 1) * 32;        // 2 row groups of 32
    int wcol = (wid >> 1) * 32;       // 4 col groups of 32
    const float* hb = g_h + (size_t)bi * PLANE;

    __shared__ __align__(16) char sBuf[12288];
    __nv_bfloat16* sVh = (__nv_bfloat16*)sBuf;            // [64][16]
    __nv_bfloat16* sVl = (__nv_bfloat16*)(sBuf + 2048);   // [64][16]
    __nv_bfloat16* sXh = (__nv_bfloat16*)(sBuf + 4096);   // [128][16]
    __nv_bfloat16* sXl = (__nv_bfloat16*)(sBuf + 8192);   // [128][16]

    int isY = (blockIdx.x < 3);
    int c0out = isY ? blockIdx.x * 128 : (blockIdx.x - 3) * 128;  // output col base
    int nChunks = isY ? (KPY / 16) : (KPX / 16);
    int Lout = isY ? NX : MY;
    const unsigned* gVh = (const unsigned*)(isY ? g_Vych : g_Vxch);
    const unsigned* gVl = (const unsigned*)(isY ? g_Vycl : g_Vxcl);
    int vstride = (isY ? KPY : KPX) >> 1;    // row stride in u32

    float d[2][4][4];
#pragma unroll
    for (int rt = 0; rt < 2; rt++)
#pragma unroll
        for (int c = 0; c < 4; c++)
#pragma unroll
            for (int j = 0; j < 4; j++) d[rt][c][j] = 0.f;

    for (int kc = 0; kc < nChunks; kc++) {
        int k0 = kc * 16;
        // stage V chunk: [64][16] bf16 = 512 u32 per array
        for (int idx = tid; idx < 512; idx += 256) {
            int r = idx >> 3, w = idx & 7;
            ((unsigned*)sVh)[idx] = gVh[r * vstride + (k0 >> 1) + w];
            ((unsigned*)sVl)[idx] = gVl[r * vstride + (k0 >> 1) + w];
        }
        // stage X chunk: [128 cols][16 k] with fp32->bf16 split
        if (isY) {
            // X[n][kk] = H[k0+kk][n0+n]
            for (int idx = tid; idx < 2048; idx += 256) {
                int n = idx & 127, kk = idx >> 7;
                int gm = k0 + kk, gn = c0out + n;
                float v = (gm < MY && gn < NX) ? hb[gm * NX + gn] : 0.f;
                __nv_bfloat16 h16, l16; bsplit(v, h16, l16);
                sXh[n * 16 + kk] = h16; sXl[n * 16 + kk] = l16;
            }
        } else {
            // X[m][kk] = H[m0+m][k0+kk]
            for (int idx = tid; idx < 2048; idx += 256) {
                int kk = idx & 15, m = idx >> 4;
                int gm = c0out + m, gn = k0 + kk;
                float v = (gm < MY && gn < NX) ? hb[gm * NX + gn] : 0.f;
                __nv_bfloat16 h16, l16; bsplit(v, h16, l16);
                sXh[m * 16 + kk] = h16; sXl[m * 16 + kk] = l16;
            }
        }
        __syncthreads();

        // fragment loads
        int kp = (lane & 3) * 2;
        int rgrp = lane >> 2;
        unsigned ah[2][4], al[2][4];
#pragma unroll
        for (int rt = 0; rt < 2; rt++) {
            int r = wrow + rt * 16 + rgrp;
            ah[rt][0] = *(const unsigned*)&sVh[r * 16 + kp];
            ah[rt][1] = *(const unsigned*)&sVh[(r + 8) * 16 + kp];
            ah[rt][2] = *(const unsigned*)&sVh[r * 16 + kp + 8];
            ah[rt][3] = *(const unsigned*)&sVh[(r + 8) * 16 + kp + 8];
            al[rt][0] = *(const unsigned*)&sVl[r * 16 + kp];
            al[rt][1] = *(const unsigned*)&sVl[(r + 8) * 16 + kp];
            al[rt][2] = *(const unsigned*)&sVl[r * 16 + kp + 8];
            al[rt][3] = *(const unsigned*)&sVl[(r + 8) * 16 + kp + 8];
        }
        unsigned bh[4][2], bl[4][2];
#pragma unroll
        for (int c = 0; c < 4; c++) {
            int n = wcol + c * 8 + rgrp;
            bh[c][0] = *(const unsigned*)&sXh[n * 16 + kp];
            bh[c][1] = *(const unsigned*)&sXh[n * 16 + kp + 8];
            bl[c][0] = *(const unsigned*)&sXl[n * 16 + kp];
            bl[c][1] = *(const unsigned*)&sXl[n * 16 + kp + 8];
        }
#pragma unroll
        for (int rt = 0; rt < 2; rt++)
#pragma unroll
            for (int c = 0; c < 4; c++) {
                mma16816(d[rt][c], ah[rt], bh[c]);
                mma16816(d[rt][c], ah[rt], bl[c]);
                mma16816(d[rt][c], al[rt], bh[c]);
            }
        __syncthreads();
    }

    // epilogue
    float* outr = isY ? g_ftyr : g_ftxr;
    float* outi = isY ? g_ftyi : g_ftxi;
#pragma unroll
    for (int rt = 0; rt < 2; rt++) {
        int r0 = wrow + rt * 16 + (lane >> 2);
#pragma unroll
        for (int c = 0; c < 4; c++) {
            int col = c0out + wcol + c * 8 + (lane & 3) * 2;
            if (col < Lout) {
                int k0m = r0 & 31;
                float* base0 = (r0 < 32 ? outr : outi);
                *(float2*)&base0[((size_t)bi * KM + k0m) * Lout + col] =
                    make_float2(d[rt][c][0], d[rt][c][1]);
                int r2 = r0 + 8;
                int k2m = r2 & 31;
                float* base2 = (r2 < 32 ? outr : outi);
                *(float2*)&base2[((size_t)bi * KM + k2m) * Lout + col] =
                    make_float2(d[rt][c][2], d[rt][c][3]);
            }
        }
    }
}

// ---------------- fused mode mix (two-phase cp.async overlap) ----------------
__global__ void __launch_bounds__(256) mixFK(const float* __restrict__ fw1,
                                             const float* __restrict__ fw2) {
    int isY = (blockIdx.x < 3);
    const float* fw = isY ? fw1 : fw2;
    const float* finr = isY ? g_ftyr : g_ftxr;
    const float* fini = isY ? g_ftyi : g_ftxi;
    float* foutr = isY ? g_oyr : g_oxr;
    float* fouti = isY ? g_oyi : g_oxi;
    int L = isY ? NX : MY;
    int l0 = (isY ? blockIdx.x : (blockIdx.x - 3)) * 128;

    int b = blockIdx.z, k = blockIdx.y;
    int tid = threadIdx.x;
    int og = tid >> 5, lg = tid & 31;

    __shared__ float  sWr[32][32], sWi[32][32];
    __shared__ float4 sFr[32][32], sFi[32][32];

    for (int idx = tid; idx < 512; idx += 256) {
        int i = idx >> 5, l4 = idx & 31;
        int gl = l0 + l4 * 4;
        size_t off = ((size_t)(b * CW + i) * KM + k) * L + gl;
        int sz = (gl < L) ? 16 : 0;
        cpa16(&sFr[i][l4], &finr[off], sz);
        cpa16(&sFi[i][l4], &fini[off], sz);
    }
    CPA_COMMIT();
    for (int idx = 512 + tid; idx < 1024; idx += 256) {
        int i = idx >> 5, l4 = idx & 31;
        int gl = l0 + l4 * 4;
        size_t off = ((size_t)(b * CW + i) * KM + k) * L + gl;
        int sz = (gl < L) ? 16 : 0;
        cpa16(&sFr[i][l4], &finr[off], sz);
        cpa16(&sFi[i][l4], &fini[off], sz);
    }
    CPA_COMMIT();
    for (int idx = tid; idx < 1024; idx += 256) {
        int i = idx >> 5, o = idx & 31;
        const float* p = fw + ((size_t)(i * 32 + o) * KM + k) * 2;
        sWr[i][o] = p[0]; sWi[i][o] = p[1];
    }

    float cr[4][4], ci[4][4];
#pragma unroll
    for (int a = 0; a < 4; a++)
#pragma unroll
        for (int j = 0; j < 4; j++) { cr[a][j] = 0.f; ci[a][j] = 0.f; }

    CPA_WAIT1();
    __syncthreads();

#pragma unroll 4
    for (int i = 0; i < 16; i++) {
        float4 fr4 = sFr[i][lg], fi4 = sFi[i][lg];
        float fr[4] = {fr4.x, fr4.y, fr4.z, fr4.w};
        float fi[4] = {fi4.x, fi4.y, fi4.z, fi4.w};
        float4 wr4 = *(const float4*)&sWr[i][og * 4];
        float4 wi4 = *(const float4*)&sWi[i][og * 4];
        float wr[4] = {wr4.x, wr4.y, wr4.z, wr4.w};
        float wi[4] = {wi4.x, wi4.y, wi4.z, wi4.w};
#pragma unroll
        for (int a = 0; a < 4; a++) {
            float wrv = wr[a], wiv = wi[a];
#pragma unroll
            for (int j = 0; j < 4; j++) {
                cr[a][j] = fmaf(wrv, fr[j], cr[a][j]);
                cr[a][j] = fmaf(-wiv, fi[j], cr[a][j]);
                ci[a][j] = fmaf(wrv, fi[j], ci[a][j]);
                ci[a][j] = fmaf(wiv, fr[j], ci[a][j]);
            }
        }
    }

    CPA_WAIT0();
    __syncthreads();

#pragma unroll 4
    for (int i = 16; i < 32; i++) {
        float4 fr4 = sFr[i][lg], fi4 = sFi[i][lg];
        float fr[4] = {fr4.x, fr4.y, fr4.z, fr4.w};
        float fi[4] = {fi4.x, fi4.y, fi4.z, fi4.w};
        float4 wr4 = *(const float4*)&sWr[i][og * 4];
        float4 wi4 = *(const float4*)&sWi[i][og * 4];
        float wr[4] = {wr4.x, wr4.y, wr4.z, wr4.w};
        float wi[4] = {wi4.x, wi4.y, wi4.z, wi4.w};
#pragma unroll
        for (int a = 0; a < 4; a++) {
            float wrv = wr[a], wiv = wi[a];
#pragma unroll
            for (int j = 0; j < 4; j++) {
                cr[a][j] = fmaf(wrv, fr[j], cr[a][j]);
                cr[a][j] = fmaf(-wiv, fi[j], cr[a][j]);
                ci[a][j] = fmaf(wrv, fi[j], ci[a][j]);
                ci[a][j] = fmaf(wiv, fr[j], ci[a][j]);
            }
        }
    }

    int gl = l0 + lg * 4;
    if (gl < L) {
#pragma unroll
        for (int a = 0; a < 4; a++) {
            int o = og * 4 + a;
            size_t off = ((size_t)(b * CW + o) * KM + k) * L + gl;
            *(float4*)&foutr[off] = make_float4(cr[a][0], cr[a][1], cr[a][2], cr[a][3]);
            *(float4*)&fouti[off] = make_float4(ci[a][0], ci[a][1], ci[a][2], ci[a][3]);
        }
    }
}

// ---------------- fused inverse: x1 = invY + invX, 4 k-chunks of 8, double buffered ----------------
__global__ void __launch_bounds__(256) invK() {
    int bo = blockIdx.z;
    int m0 = blockIdx.y * 64;
    int n0 = blockIdx.x * 64;
    int tid = threadIdx.x;
    int mg = tid >> 4, ng = tid & 15;
    int mlim = (m0 == 128) ? 13 : 16;
    int nlim = (n0 == 320) ? 10 : 16;

    __shared__ float4 sVyr[2][8][16], sVyi[2][8][16], sOxr[2][8][16], sOxi[2][8][16];
    __shared__ float4 sOyr[2][8][16], sOyi[2][8][16], sVxr[2][8][16], sVxi[2][8][16];

    float acc[4][4];
#pragma unroll
    for (int a = 0; a < 4; a++)
#pragma unroll
        for (int j = 0; j < 4; j++) acc[a][j] = 0.f;

    if (tid < 128) {
        int kk = tid >> 4, q = tid & 15;
        int kabs = kk;
        int msz = (q < mlim) ? 16 : 0;
        int nsz = (q < nlim) ? 16 : 0;
        size_t obY = ((size_t)bo * KM + kabs) * NX + n0 + q * 4;
        size_t obX = ((size_t)bo * KM + kabs) * MY + m0 + q * 4;
        cpa16(&sVyr[0][kk][q], &g_Vyr[kabs * MY + m0 + q * 4], msz);
        cpa16(&sVyi[0][kk][q], &g_Vyi[kabs * MY + m0 + q * 4], msz);
        cpa16(&sOxr[0][kk][q], &g_oxr[obX], msz);
        cpa16(&sOxi[0][kk][q], &g_oxi[obX], msz);
        cpa16(&sOyr[0][kk][q], &g_oyr[obY], nsz);
        cpa16(&sOyi[0][kk][q], &g_oyi[obY], nsz);
        cpa16(&sVxr[0][kk][q], &g_Vxr[kabs * NX + n0 + q * 4], nsz);
        cpa16(&sVxi[0][kk][q], &g_Vxi[kabs * NX + n0 + q * 4], nsz);
    }
    CPA_COMMIT();

    for (int c = 0; c < 4; c++) {
        if (c < 3) {
            int buf = (c + 1) & 1;
            if (tid < 128) {
                int kk = tid >> 4, q = tid & 15;
                int kabs = (c + 1) * 8 + kk;
                int msz = (q < mlim) ? 16 : 0;
                int nsz = (q < nlim) ? 16 : 0;
                size_t obY = ((size_t)bo * KM + kabs) * NX + n0 + q * 4;
                size_t obX = ((size_t)bo * KM + kabs) * MY + m0 + q * 4;
                cpa16(&sVyr[buf][kk][q], &g_Vyr[kabs * MY + m0 + q * 4], msz);
                cpa16(&sVyi[buf][kk][q], &g_Vyi[kabs * MY + m0 + q * 4], msz);
                cpa16(&sOxr[buf][kk][q], &g_oxr[obX], msz);
                cpa16(&sOxi[buf][kk][q], &g_oxi[obX], msz);
                cpa16(&sOyr[buf][kk][q], &g_oyr[obY], nsz);
                cpa16(&sOyi[buf][kk][q], &g_oyi[obY], nsz);
                cpa16(&sVxr[buf][kk][q], &g_Vxr[kabs * NX + n0 + q * 4], nsz);
                cpa16(&sVxi[buf][kk][q], &g_Vxi[kabs * NX + n0 + q * 4], nsz);
            }
            CPA_COMMIT();
            CPA_WAIT1();
        } else {
            CPA_WAIT0();
        }
        __syncthreads();

        int cur = c & 1;
#pragma unroll
        for (int j = 0; j < 8; j++) {
            float4 vyr4 = sVyr[cur][j][mg], vyi4 = sVyi[cur][j][mg];
            float4 oxr4 = sOxr[cur][j][mg], oxi4 = sOxi[cur][j][mg];
            float4 oyr4 = sOyr[cur][j][ng], oyi4 = sOyi[cur][j][ng];
            float4 vxr4 = sVxr[cur][j][ng], vxi4 = sVxi[cur][j][ng];
            float vyr[4] = {vyr4.x, vyr4.y, vyr4.z, vyr4.w};
            float vyi[4] = {vyi4.x, vyi4.y, vyi4.z, vyi4.w};
            float oxr[4] = {oxr4.x, oxr4.y, oxr4.z, oxr4.w};
            float oxi[4] = {oxi4.x, oxi4.y, oxi4.z, oxi4.w};
            float oyr[4] = {oyr4.x, oyr4.y, oyr4.z, oyr4.w};
            float oyi[4] = {oyi4.x, oyi4.y, oyi4.z, oyi4.w};
            float vxr[4] = {vxr4.x, vxr4.y, vxr4.z, vxr4.w};
            float vxi[4] = {vxi4.x, vxi4.y, vxi4.z, vxi4.w};
#pragma unroll
            for (int a = 0; a < 4; a++)
#pragma unroll
                for (int q2 = 0; q2 < 4; q2++) {
                    float s = acc[a][q2];
                    s = fmaf(vyr[a], oyr[q2], s);
                    s = fmaf(vyi[a], oyi[q2], s);
                    s = fmaf(oxr[a], vxr[q2], s);
                    s = fmaf(oxi[a], vxi[q2], s);
                    acc[a][q2] = s;
                }
        }
        __syncthreads();
    }

    if (ng < nlim && mg < mlim) {
        float* xb = g_x1 + (size_t)bo * PLANE;
        int n = n0 + ng * 4;
#pragma unroll
        for (int a = 0; a < 4; a++) {
            int m = m0 + mg * 4 + a;
            *(float4*)&xb[m * NX + n] =
                make_float4(acc[a][0], acc[a][1], acc[a][2], acc[a][3]);
        }
    }
}

// ---------------- pointwise MLP + residual ----------------
__global__ void __launch_bounds__(256) pwK(const float* __restrict__ w1, const float* __restrict__ b1,
                    const float* __restrict__ w2, const float* __restrict__ b2,
                    int applyGelu) {
    __shared__ float sX[32][128];
    __shared__ float sT[32][132];
    __shared__ float sW1[32][32], sW2[32][32];
    __shared__ float sB1[32], sB2[32];
    int tid = threadIdx.x;
    for (int idx = tid; idx < 1024; idx += 256) {
        int o = idx >> 5, c = idx & 31;
        sW1[c][o] = w1[o * 32 + c];
        sW2[c][o] = w2[o * 32 + c];
    }
    if (tid < 32) { sB1[tid] = b1[tid]; sB2[tid] = b2[tid]; }

    int p0 = blockIdx.x * 128;
    {
        int pp = tid & 127, ch = (tid >> 7) * 16;
        int p = p0 + pp;
        int b = p / PLANE, mn = p % PLANE;
        const float* src = g_x1 + ((size_t)b * CW + ch) * PLANE + mn;
#pragma unroll
        for (int cc = 0; cc < 16; cc++) sX[ch + cc][pp] = src[(size_t)cc * PLANE];
    }
    __syncthreads();

    int og = tid >> 5, pg = tid & 31;
    {
        float t[4][4];
#pragma unroll
        for (int a = 0; a < 4; a++) {
            float bb = sB1[og * 4 + a];
#pragma unroll
            for (int j = 0; j < 4; j++) t[a][j] = bb;
        }
#pragma unroll 4
        for (int c = 0; c < 32; c++) {
            float4 x4 = *(const float4*)&sX[c][pg * 4];
            float xv[4] = {x4.x, x4.y, x4.z, x4.w};
            float4 w4 = *(const float4*)&sW1[c][og * 4];
            float wv[4] = {w4.x, w4.y, w4.z, w4.w};
#pragma unroll
            for (int a = 0; a < 4; a++)
#pragma unroll
                for (int j = 0; j < 4; j++) t[a][j] = fmaf(wv[a], xv[j], t[a][j]);
        }
#pragma unroll
        for (int a = 0; a < 4; a++)
            *(float4*)&sT[og * 4 + a][pg * 4] =
                make_float4(geluf(t[a][0]), geluf(t[a][1]), geluf(t[a][2]), geluf(t[a][3]));
    }
    __syncthreads();
    {
        float t[4][4];
#pragma unroll
        for (int a = 0; a < 4; a++) {
            float bb = sB2[og * 4 + a];
#pragma unroll
            for (int j = 0; j < 4; j++) t[a][j] = bb;
        }
#pragma unroll 4
        for (int c = 0; c < 32; c++) {
            float4 x4 = *(const float4*)&sT[c][pg * 4];
            float xv[4] = {x4.x, x4.y, x4.z, x4.w};
            float4 w4 = *(const float4*)&sW2[c][og * 4];
            float wv[4] = {w4.x, w4.y, w4.z, w4.w};
#pragma unroll
            for (int a = 0; a < 4; a++)
#pragma unroll
                for (int j = 0; j < 4; j++) t[a][j] = fmaf(wv[a], xv[j], t[a][j]);
        }
        int pbase = p0 + pg * 4;
#pragma unroll
        for (int a = 0; a < 4; a++) {
            int o = og * 4 + a;
#pragma unroll
            for (int j = 0; j < 4; j++) {
                int p = pbase + j;
                int b = p / PLANE, mn = p % PLANE;
                size_t off = ((size_t)b * CW + o) * PLANE + mn;
                float s = t[a][j];
                if (applyGelu) s = geluf(s);
                g_h[off] += s;
            }
        }
    }
}

// ---------------- final head ----------------
__global__ void __launch_bounds__(256) finalK(const float* __restrict__ fc1w, const float* __restrict__ fc1b,
                       const float* __restrict__ fc2w, const float* __restrict__ fc2b,
                       float* __restrict__ out) {
    __shared__ float sX[32][68];
    __shared__ float sW1h[32][64];
    __shared__ float sT[64][68];
    __shared__ float sw2[128], sb1[128];
    __shared__ float sRed[4][64];
    int tid = threadIdx.x;
    if (tid < 128) { sw2[tid] = fc2w[tid]; sb1[tid] = fc1b[tid]; }

    int p0 = blockIdx.x * 64;
    {
        int pp = tid & 63, ch = (tid >> 6) * 8;
        int p = p0 + pp;
        int b = p / PLANE, mn = p % PLANE;
        const float* src = g_h + ((size_t)b * CW + ch) * PLANE + mn;
#pragma unroll
        for (int cc = 0; cc < 8; cc++) sX[ch + cc][pp] = src[(size_t)cc * PLANE];
    }

    float part = 0.f;
    for (int jh = 0; jh < 128; jh += 64) {
        __syncthreads();
        for (int idx = tid; idx < 512; idx += 256) {
            int c = idx >> 4, j4 = idx & 15;
            *(float4*)&sW1h[c][j4 * 4] = *(const float4*)&fc1w[c * 128 + jh + j4 * 4];
        }
        __syncthreads();

        int jg = tid >> 4, pgr = tid & 15;
        float t[4][4];
#pragma unroll
        for (int a = 0; a < 4; a++) {
            float bb = sb1[jh + jg * 4 + a];
#pragma unroll
            for (int j = 0; j < 4; j++) t[a][j] = bb;
        }
#pragma unroll 4
        for (int c = 0; c < 32; c++) {
            float4 x4 = *(const float4*)&sX[c][pgr * 4];
            float xv[4] = {x4.x, x4.y, x4.z, x4.w};
            float4 w4 = *(const float4*)&sW1h[c][jg * 4];
            float wv[4] = {w4.x, w4.y, w4.z, w4.w};
#pragma unroll
            for (int a = 0; a < 4; a++)
#pragma unroll
                for (int j = 0; j < 4; j++) t[a][j] = fmaf(wv[a], xv[j], t[a][j]);
        }
#pragma unroll
        for (int a = 0; a < 4; a++)
            *(float4*)&sT[jg * 4 + a][pgr * 4] =
                make_float4(geluf(t[a][0]), geluf(t[a][1]), geluf(t[a][2]), geluf(t[a][3]));
        __syncthreads();
        {
            int pq = tid & 63, jq = tid >> 6;
            float s = 0.f;
#pragma unroll
            for (int jj = 0; jj < 16; jj++) {
                int j = jq * 16 + jj;
                s = fmaf(sw2[jh + j], sT[j][pq], s);
            }
            part += s;
        }
    }
    __syncthreads();
    {
        int pq = tid & 63, jq = tid >> 6;
        sRed[jq][pq] = part;
    }
    __syncthreads();
    if (tid < 64) {
        out[p0 + tid] = sRed[0][tid] + sRed[1][tid] + sRed[2][tid] + sRed[3][tid] + fc2b[0];
    }
}

// ---------------- launch ----------------
extern "C" void kernel_launch(void* const* d_in, const int* in_sizes, int n_in,
                              void* d_out, int out_size) {
    (void)in_sizes; (void)n_in; (void)out_size;
    const float* x    = (const float*)d_in[0];
    const float* sx   = (const float*)d_in[1];
    const float* sy   = (const float*)d_in[2];
    const float* fc0w = (const float*)d_in[3];
    const float* fc0b = (const float*)d_in[4];
    const float* fw1  = (const float*)d_in[5];
    const float* fw2  = (const float*)d_in[6];
    const float* w1   = (const float*)d_in[7];
    const float* b1   = (const float*)d_in[8];
    const float* w2   = (const float*)d_in[9];
    const float* b2   = (const float*)d_in[10];
    const float* fc1w = (const float*)d_in[11];
    const float* fc1b = (const float*)d_in[12];
    const float* fc2w = (const float*)d_in[13];
    const float* fc2b = (const float*)d_in[14];
    float* out = (float*)d_out;

    precomputeK<<<64, 256>>>(sx, sy);
    fc0K<<<PIX / 128, 256>>>(x, fc0w, fc0b);

    for (int blk = 0; blk < 4; blk++) {
        const float* fw1p = fw1 + (size_t)blk * CW * CW * KM * 2;
        const float* fw2p = fw2 + (size_t)blk * CW * CW * KM * 2;
        const float* w1p  = w1 + (size_t)blk * CW * CW;
        const float* b1p  = b1 + (size_t)blk * CW;
        const float* w2p  = w2 + (size_t)blk * CW * CW;
        const float* b2p  = b2 + (size_t)blk * CW;

        ftK<<<dim3(5, BSZ * CW), 256>>>();
        mixFK<<<dim3(5, KM, BSZ), 256>>>(fw1p, fw2p);
        invK<<<dim3(6, 3, BSZ * CW), 256>>>();
        pwK<<<PIX / 128, 256>>>(w1p, b1p, w2p, b2p, blk < 3 ? 1 : 0);
    }

    finalK<<<PIX / 64, 256>>>(fc1w, fc1b, fc2w, fc2b, out);
}